// round 1
// baseline (speedup 1.0000x reference)
#include <cuda_runtime.h>
#include <math.h>

#define NN 32768
#define FF 64
#define HH 4
#define HFD 256
#define ESZ 524288
#define EGZ 524288
#define GG 64
#define NCC 10
#define BNEPS 1e-5f

// ---------------- scratch arena (static __device__; no runtime allocs) -------
#define O_B0   0
#define O_BR   (O_B0 + NN*FF)          // 3 raw scatter results (branches 1..3)
#define O_X    (O_BR + 3*NN*FF)        // x1..x3
#define O_H    (O_X + 3*NN*FF)         // h  [N,256]
#define O_ATT  (O_H + NN*HFD)          // gat out [N,256]
#define O_AS   (O_ATT + NN*HFD)
#define O_AD   (O_AS + NN*HH)
#define O_M    (O_AD + NN*HH)
#define O_DEN  (O_M + NN*HH)
#define O_INV  (O_DEN + NN*HH)
#define O_EX   (O_INV + NN*HH)         // exp values per edge [E,4]
#define O_Z    (O_EX + EGZ*HH)
#define O_XACC (O_Z + NN*FF)
#define O_STATS (O_XACC + NN*FF)       // 256 floats: sum, ssq, mu, rstd
#define O_POOL (O_STATS + 256)
#define O_Y1   (O_POOL + GG*FF)
#define O_Y2   (O_Y1 + GG*256)
#define O_Y3   (O_Y2 + GG*128)
#define ARENA_SZ (O_Y3 + GG*16)

__device__ __align__(256) float g_arena[ARENA_SZ];

// ---------------- helpers ----------------------------------------------------
__device__ __forceinline__ void red4(float* a, float4 v) {
    asm volatile("red.global.add.v4.f32 [%0], {%1,%2,%3,%4};"
                 :: "l"(a), "f"(v.x), "f"(v.y), "f"(v.z), "f"(v.w) : "memory");
}
__device__ __forceinline__ float lrelu(float v) { return v > 0.f ? v : 0.2f * v; }
__device__ __forceinline__ float eluf(float v)  { return v > 0.f ? v : __expf(v) - 1.f; }
__device__ __forceinline__ void amaxf(float* a, float v) {
    if (v >= 0.f) atomicMax((int*)a, __float_as_int(v));
    else          atomicMin((unsigned int*)a, __float_as_uint(v));
}

// ---------------- stage A: scatter passes ------------------------------------
// out[dst] += attr[e] * f(x[src]);  16 threads per edge, float4 per thread
__global__ __launch_bounds__(256) void k_scatter(
    const int* __restrict__ src, const int* __restrict__ dst,
    const float* __restrict__ attr, const float* __restrict__ xin,
    float* __restrict__ outb, int doAbs)
{
    int t = blockIdx.x * 256 + threadIdx.x;
    int e = t >> 4, lane = t & 15;
    int s = src[e], d = dst[e];
    float a = attr[e];
    float4 v = ((const float4*)xin)[s * 16 + lane];
    if (doAbs) { v.x = fabsf(v.x); v.y = fabsf(v.y); v.z = fabsf(v.z); v.w = fabsf(v.w); }
    v.x *= a; v.y *= a; v.z *= a; v.w *= a;
    red4(outb + d * 64 + lane * 4, v);
}

// ---------------- GEMM1: h = xin[N,64] @ W[64,256] ---------------------------
// block: 256 thr, 16 rows; thread: 4 rows x 4 cols
__global__ __launch_bounds__(256) void k_gemm_h(
    const float* __restrict__ xin, const float* __restrict__ W, float* __restrict__ h)
{
    __shared__ float xs[16 * 64];
    int t = threadIdx.x;
    int row0 = blockIdx.x * 16;
    ((float4*)xs)[t] = ((const float4*)(xin + row0 * 64))[t];
    __syncthreads();
    int tx = t & 63, ty = t >> 6;
    float4 acc[4];
    acc[0] = acc[1] = acc[2] = acc[3] = make_float4(0.f, 0.f, 0.f, 0.f);
    const float4* W4 = (const float4*)W;
#pragma unroll 8
    for (int k = 0; k < 64; k++) {
        float4 w = W4[k * 64 + tx];
#pragma unroll
        for (int ri = 0; ri < 4; ri++) {
            float xv = xs[(ty * 4 + ri) * 64 + k];
            acc[ri].x += xv * w.x; acc[ri].y += xv * w.y;
            acc[ri].z += xv * w.z; acc[ri].w += xv * w.w;
        }
    }
#pragma unroll
    for (int ri = 0; ri < 4; ri++)
        ((float4*)h)[(row0 + ty * 4 + ri) * 64 + tx] = acc[ri];
}

// ---------------- attention coefficients a_s, a_d [N,4] ----------------------
__global__ __launch_bounds__(256) void k_attcoef(
    const float* __restrict__ h, const float* __restrict__ asrc,
    const float* __restrict__ adst, float* __restrict__ as_, float* __restrict__ ad_)
{
    int t = blockIdx.x * 256 + threadIdx.x;
    int n = t >> 2, hd = t & 3;
    const float4* h4 = (const float4*)(h + n * 256 + hd * 64);
    const float4* s4 = (const float4*)(asrc + hd * 64);
    const float4* d4 = (const float4*)(adst + hd * 64);
    float ss = 0.f, dd = 0.f;
#pragma unroll
    for (int i = 0; i < 16; i++) {
        float4 hv = h4[i], sv = s4[i], dv = d4[i];
        ss += hv.x * sv.x + hv.y * sv.y + hv.z * sv.z + hv.w * sv.w;
        dd += hv.x * dv.x + hv.y * dv.y + hv.z * dv.z + hv.w * dv.w;
    }
    as_[t] = ss; ad_[t] = dd;
}

// self-loop max init: m[n] = lrelu(a_s[n]+a_d[n])
__global__ __launch_bounds__(256) void k_initm(
    const float* __restrict__ as_, const float* __restrict__ ad_, float* __restrict__ m)
{
    int n = blockIdx.x * 256 + threadIdx.x;
    float4 s = ((const float4*)as_)[n], d = ((const float4*)ad_)[n];
    float4 o;
    o.x = lrelu(s.x + d.x); o.y = lrelu(s.y + d.y);
    o.z = lrelu(s.z + d.z); o.w = lrelu(s.w + d.w);
    ((float4*)m)[n] = o;
}

__global__ __launch_bounds__(256) void k_edgemax(
    const int* __restrict__ ei, const float* __restrict__ as_,
    const float* __restrict__ ad_, float* __restrict__ m)
{
    int e = blockIdx.x * 256 + threadIdx.x;
    int s = ei[e], d = ei[EGZ + e];
    float4 sv = ((const float4*)as_)[s], dv = ((const float4*)ad_)[d];
    amaxf(&m[d * 4 + 0], lrelu(sv.x + dv.x));
    amaxf(&m[d * 4 + 1], lrelu(sv.y + dv.y));
    amaxf(&m[d * 4 + 2], lrelu(sv.z + dv.z));
    amaxf(&m[d * 4 + 3], lrelu(sv.w + dv.w));
}

// denom init with self contribution
__global__ __launch_bounds__(256) void k_initden(
    const float* __restrict__ as_, const float* __restrict__ ad_,
    const float* __restrict__ m, float* __restrict__ den)
{
    int n = blockIdx.x * 256 + threadIdx.x;
    float4 s = ((const float4*)as_)[n], d = ((const float4*)ad_)[n];
    float4 mm = ((const float4*)m)[n];
    float4 o;
    o.x = __expf(lrelu(s.x + d.x) - mm.x);
    o.y = __expf(lrelu(s.y + d.y) - mm.y);
    o.z = __expf(lrelu(s.z + d.z) - mm.z);
    o.w = __expf(lrelu(s.w + d.w) - mm.w);
    ((float4*)den)[n] = o;
}

__global__ __launch_bounds__(256) void k_edgesum(
    const int* __restrict__ ei, const float* __restrict__ as_,
    const float* __restrict__ ad_, const float* __restrict__ m,
    float* __restrict__ den, float* __restrict__ ex)
{
    int e = blockIdx.x * 256 + threadIdx.x;
    int s = ei[e], d = ei[EGZ + e];
    float4 sv = ((const float4*)as_)[s], dv = ((const float4*)ad_)[d];
    float4 mm = ((const float4*)m)[d];
    float4 o;
    o.x = __expf(lrelu(sv.x + dv.x) - mm.x);
    o.y = __expf(lrelu(sv.y + dv.y) - mm.y);
    o.z = __expf(lrelu(sv.z + dv.z) - mm.z);
    o.w = __expf(lrelu(sv.w + dv.w) - mm.w);
    ((float4*)ex)[e] = o;
    red4(den + d * 4, o);
}

__global__ __launch_bounds__(256) void k_invden(
    const float* __restrict__ den, float* __restrict__ inv)
{
    int t = blockIdx.x * 256 + threadIdx.x;
    inv[t] = 1.0f / den[t];
}

// out[n] = alpha_self * h[n]   (initializes att, no atomics)
__global__ __launch_bounds__(256) void k_initout(
    const float* __restrict__ as_, const float* __restrict__ ad_,
    const float* __restrict__ m, const float* __restrict__ inv,
    const float* __restrict__ h, float* __restrict__ att)
{
    int t = blockIdx.x * 256 + threadIdx.x;
    int n = t >> 6, gq = t & 63, hd = gq >> 4;
    float a = as_[n * 4 + hd], b = ad_[n * 4 + hd];
    float alpha = __expf(lrelu(a + b) - m[n * 4 + hd]) * inv[n * 4 + hd];
    float4 hv = ((const float4*)h)[n * 64 + gq];
    hv.x *= alpha; hv.y *= alpha; hv.z *= alpha; hv.w *= alpha;
    ((float4*)att)[n * 64 + gq] = hv;
}

// att[dst] += alpha(e) * h[src];  64 threads per edge
__global__ __launch_bounds__(256) void k_edgeaggr(
    const int* __restrict__ ei, const float* __restrict__ ex,
    const float* __restrict__ inv, const float* __restrict__ h, float* __restrict__ att)
{
    int t = blockIdx.x * 256 + threadIdx.x;
    int e = t >> 6, gq = t & 63, hd = gq >> 4;
    int s = ei[e], d = ei[EGZ + e];
    float alpha = ex[e * 4 + hd] * inv[d * 4 + hd];
    float4 hv = ((const float4*)h)[s * 64 + gq];
    hv.x *= alpha; hv.y *= alpha; hv.z *= alpha; hv.w *= alpha;
    red4(att + d * 256 + gq * 4, hv);
}

// ---------------- GEMM2: z = elu(att + bias)[N,256] @ W[256,64] --------------
// block: 256 thr, 64 rows; thread: 4 rows x 4 cols; k-chunks of 64 in smem
__global__ __launch_bounds__(256) void k_gemm_z(
    const float* __restrict__ att, const float* __restrict__ bias,
    const float* __restrict__ W, float* __restrict__ z)
{
    __shared__ float As[64 * 65];
    int t = threadIdx.x;
    int row0 = blockIdx.x * 64;
    int tx = t & 15, ty = t >> 4;
    float4 acc[4];
    acc[0] = acc[1] = acc[2] = acc[3] = make_float4(0.f, 0.f, 0.f, 0.f);
    const float4* W4 = (const float4*)W;
    for (int kc = 0; kc < 4; kc++) {
        __syncthreads();
        for (int i = t; i < 1024; i += 256) {
            int r = i >> 4, c4 = i & 15;
            float4 v = ((const float4*)(att + (row0 + r) * 256 + kc * 64))[c4];
            float4 b = ((const float4*)(bias + kc * 64))[c4];
            float* dp = &As[r * 65 + c4 * 4];
            dp[0] = eluf(v.x + b.x); dp[1] = eluf(v.y + b.y);
            dp[2] = eluf(v.z + b.z); dp[3] = eluf(v.w + b.w);
        }
        __syncthreads();
#pragma unroll 8
        for (int k = 0; k < 64; k++) {
            float4 w = W4[(kc * 64 + k) * 16 + tx];
#pragma unroll
            for (int ri = 0; ri < 4; ri++) {
                float av = As[(ty * 4 + ri) * 65 + k];
                acc[ri].x += av * w.x; acc[ri].y += av * w.y;
                acc[ri].z += av * w.z; acc[ri].w += av * w.w;
            }
        }
    }
#pragma unroll
    for (int ri = 0; ri < 4; ri++)
        ((float4*)z)[(row0 + ty * 4 + ri) * 16 + tx] = acc[ri];
}

// ---------------- batchnorm over N rows --------------------------------------
__global__ __launch_bounds__(256) void k_colstats(
    const float* __restrict__ z, float* __restrict__ stats)
{
    int col = threadIdx.x & 63;
    int rr = threadIdx.x >> 6;
    int rbase = blockIdx.x * 2048;
    float s = 0.f, ss = 0.f;
    for (int r = rbase + rr; r < rbase + 2048; r += 4) {
        float v = z[r * FF + col]; s += v; ss += v * v;
    }
    atomicAdd(&stats[col], s);
    atomicAdd(&stats[FF + col], ss);
}

__global__ void k_finstats(float* stats)
{
    int c = threadIdx.x;
    float mu = stats[c] * (1.f / NN);
    float var = stats[FF + c] * (1.f / NN) - mu * mu;
    stats[128 + c] = mu;
    stats[192 + c] = rsqrtf(var + BNEPS);
}

__global__ __launch_bounds__(256) void k_bnapply(
    const float* __restrict__ z, const float* __restrict__ stats,
    const float* __restrict__ g, const float* __restrict__ be, float* __restrict__ xacc)
{
    int t = blockIdx.x * 256 + threadIdx.x;
    int f = t & 63;
    xacc[t] += (z[t] - stats[128 + f]) * stats[192 + f] * g[f] + be[f];
}

// ---------------- pooling ----------------------------------------------------
__global__ __launch_bounds__(256) void k_pool(
    const float* __restrict__ xacc, const int* __restrict__ batch, float* __restrict__ pool)
{
    int t = blockIdx.x * 256 + threadIdx.x;
    int n = t >> 4, q = t & 15;
    int b = batch[n];
    float4 v = ((const float4*)xacc)[n * 16 + q];
    red4(pool + b * 64 + q * 4, v);
}

// ---------------- FC head (rows=64) ------------------------------------------
// fc1: [64,64]@[64,256]; one warp per output row
__global__ __launch_bounds__(256) void k_fc1(
    const float* __restrict__ A, const float* __restrict__ W,
    const float* __restrict__ b, float* __restrict__ Y)
{
    int r = blockIdx.x * 8 + (threadIdx.x >> 5);
    int lane = threadIdx.x & 31;
    const float4* W4 = (const float4*)W;
    float4 acc0 = ((const float4*)b)[lane];
    float4 acc1 = ((const float4*)b)[32 + lane];
#pragma unroll 8
    for (int k = 0; k < 64; k++) {
        float a = __ldg(&A[r * 64 + k]);
        float4 w0 = W4[k * 64 + lane];
        float4 w1 = W4[k * 64 + 32 + lane];
        acc0.x += a * w0.x; acc0.y += a * w0.y; acc0.z += a * w0.z; acc0.w += a * w0.w;
        acc1.x += a * w1.x; acc1.y += a * w1.y; acc1.z += a * w1.z; acc1.w += a * w1.w;
    }
    ((float4*)Y)[r * 64 + lane] = acc0;
    ((float4*)Y)[r * 64 + 32 + lane] = acc1;
}

// fc2: [64,256]@[256,128]
__global__ __launch_bounds__(256) void k_fc2(
    const float* __restrict__ A, const float* __restrict__ W,
    const float* __restrict__ b, float* __restrict__ Y)
{
    int r = blockIdx.x * 8 + (threadIdx.x >> 5);
    int lane = threadIdx.x & 31;
    const float4* W4 = (const float4*)W;
    float4 acc = ((const float4*)b)[lane];
#pragma unroll 8
    for (int k = 0; k < 256; k++) {
        float a = __ldg(&A[r * 256 + k]);
        float4 w = W4[k * 32 + lane];
        acc.x += a * w.x; acc.y += a * w.y; acc.z += a * w.z; acc.w += a * w.w;
    }
    ((float4*)Y)[r * 32 + lane] = acc;
}

// fc3: [64,128]@[128,10]
__global__ __launch_bounds__(256) void k_fc3(
    const float* __restrict__ A, const float* __restrict__ W,
    const float* __restrict__ b, float* __restrict__ Y)
{
    int r = blockIdx.x * 8 + (threadIdx.x >> 5);
    int lane = threadIdx.x & 31;
    float acc = (lane < NCC) ? b[lane] : 0.f;
#pragma unroll 8
    for (int k = 0; k < 128; k++) {
        float a = __ldg(&A[r * 128 + k]);
        float w = (lane < NCC) ? W[k * NCC + lane] : 0.f;
        acc += a * w;
    }
    if (lane < NCC) Y[r * NCC + lane] = acc;
}

// batchnorm over 64 rows (head), optional relu; writes to O
__global__ void k_bncol(
    const float* __restrict__ Y, float* __restrict__ O, int cols,
    const float* __restrict__ g, const float* __restrict__ be, int relu)
{
    int c = blockIdx.x * blockDim.x + threadIdx.x;
    if (c >= cols) return;
    float s = 0.f, ss = 0.f;
#pragma unroll 8
    for (int r = 0; r < GG; r++) { float v = Y[r * cols + c]; s += v; ss += v * v; }
    float mu = s * (1.f / GG);
    float var = ss * (1.f / GG) - mu * mu;
    float rs = rsqrtf(var + BNEPS);
    float gg = g[c], bb = be[c];
#pragma unroll 8
    for (int r = 0; r < GG; r++) {
        float v = (Y[r * cols + c] - mu) * rs * gg + bb;
        if (relu) v = fmaxf(v, 0.f);
        O[r * cols + c] = v;
    }
}

// ---------------- host orchestration -----------------------------------------
extern "C" void kernel_launch(void* const* d_in, const int* in_sizes, int n_in,
                              void* d_out, int out_size)
{
    const float* x      = (const float*)d_in[0];
    const int*   eidx   = (const int*)d_in[1];
    const int*   batch  = (const int*)d_in[2];
    const int*   sidx   = (const int*)d_in[3];
    const float* sattr  = (const float*)d_in[4];
    const float* gatW   = (const float*)d_in[5];
    const float* gasrc  = (const float*)d_in[6];
    const float* gadst  = (const float*)d_in[7];
    const float* gatb   = (const float*)d_in[8];
    const float* mlpW   = (const float*)d_in[9];
    const float* mlpg   = (const float*)d_in[11];
    const float* mlpbe  = (const float*)d_in[12];
    const float* fc1W   = (const float*)d_in[13];
    const float* fc1b   = (const float*)d_in[14];
    const float* fc1g   = (const float*)d_in[15];
    const float* fc1be  = (const float*)d_in[16];
    const float* fc2W   = (const float*)d_in[17];
    const float* fc2b   = (const float*)d_in[18];
    const float* fc2g   = (const float*)d_in[19];
    const float* fc2be  = (const float*)d_in[20];
    const float* fc3W   = (const float*)d_in[21];
    const float* fc3b   = (const float*)d_in[22];
    const float* fc3g   = (const float*)d_in[23];
    const float* fc3be  = (const float*)d_in[24];
    float* out = (float*)d_out;

    float* A;
    cudaGetSymbolAddress((void**)&A, g_arena);
    float* B0   = A + O_B0;
    float* BR   = A + O_BR;
    float* X123 = A + O_X;
    float* H    = A + O_H;
    float* ATT  = A + O_ATT;
    float* AS   = A + O_AS;
    float* AD   = A + O_AD;
    float* M    = A + O_M;
    float* DEN  = A + O_DEN;
    float* INV  = A + O_INV;
    float* EX   = A + O_EX;
    float* Z    = A + O_Z;
    float* XACC = A + O_XACC;
    float* ST   = A + O_STATS;
    float* POOL = A + O_POOL;
    float* Y1   = A + O_Y1;
    float* Y2   = A + O_Y2;
    float* Y3   = A + O_Y3;

    // ---- stage A: scatter preprocessing ----
    cudaMemsetAsync(B0, 0, (size_t)4 * NN * FF * sizeof(float));   // B0 + BR[0..2]
    cudaMemsetAsync(X123, 0, (size_t)3 * NN * FF * sizeof(float));

    const int SGRID = ESZ * 16 / 256;
    // b0 = scatter(idx0, attr0, x)
    k_scatter<<<SGRID, 256>>>(sidx, sidx + ESZ, sattr, x, B0, 0);
    // braw_j = scatter(idx_j, attr_j, x), j=1..3
    for (int j = 1; j <= 3; j++)
        k_scatter<<<SGRID, 256>>>(sidx + j * 2 * ESZ, sidx + j * 2 * ESZ + ESZ,
                                  sattr + j * ESZ, x, BR + (j - 1) * NN * FF, 0);
    // x_j = scatter(idx0, attr0, abs(braw_j))
    for (int j = 1; j <= 3; j++)
        k_scatter<<<SGRID, 256>>>(sidx, sidx + ESZ, sattr,
                                  BR + (j - 1) * NN * FF, X123 + (j - 1) * NN * FF, 1);

    // xacc = x
    cudaMemcpyAsync(XACC, x, (size_t)NN * FF * sizeof(float), cudaMemcpyDeviceToDevice);

    const float* bx[4] = { B0, X123, X123 + NN * FF, X123 + 2 * NN * FF };

    // ---- 4 GAT branches ----
    for (int br = 0; br < 4; br++) {
        k_gemm_h<<<NN / 16, 256>>>(bx[br], gatW + br * FF * HFD, H);
        k_attcoef<<<NN * HH / 256, 256>>>(H, gasrc + br * HH * FF, gadst + br * HH * FF, AS, AD);
        k_initm<<<NN / 256, 256>>>(AS, AD, M);
        k_edgemax<<<EGZ / 256, 256>>>(eidx, AS, AD, M);
        k_initden<<<NN / 256, 256>>>(AS, AD, M, DEN);
        k_edgesum<<<EGZ / 256, 256>>>(eidx, AS, AD, M, DEN, EX);
        k_invden<<<NN * HH / 256, 256>>>(DEN, INV);
        k_initout<<<NN * 64 / 256, 256>>>(AS, AD, M, INV, H, ATT);
        k_edgeaggr<<<EGZ * 64 / 256, 256>>>(eidx, EX, INV, H, ATT);
        k_gemm_z<<<NN / 64, 256>>>(ATT, gatb + br * HFD, mlpW + br * HFD * FF, Z);
        cudaMemsetAsync(ST, 0, 128 * sizeof(float));
        k_colstats<<<16, 256>>>(Z, ST);
        k_finstats<<<1, 64>>>(ST);
        k_bnapply<<<NN * FF / 256, 256>>>(Z, ST, mlpg + br * FF, mlpbe + br * FF, XACC);
    }

    // ---- pooling + head ----
    cudaMemsetAsync(POOL, 0, (size_t)GG * FF * sizeof(float));
    k_pool<<<NN * 16 / 256, 256>>>(XACC, batch, POOL);

    k_fc1<<<8, 256>>>(POOL, fc1W, fc1b, Y1);
    k_bncol<<<1, 256>>>(Y1, Y1, 256, fc1g, fc1be, 1);
    k_fc2<<<8, 256>>>(Y1, fc2W, fc2b, Y2);
    k_bncol<<<1, 128>>>(Y2, Y2, 128, fc2g, fc2be, 1);
    k_fc3<<<8, 256>>>(Y2, fc3W, fc3b, Y3);
    k_bncol<<<1, 32>>>(Y3, out, NCC, fc3g, fc3be, 0);
}

// round 4
// speedup vs baseline: 1.3175x; 1.3175x over previous
#include <cuda_runtime.h>
#include <math.h>

#define NN 32768
#define FF 64
#define HH 4
#define HFD 256
#define ESZ 524288
#define EGZ 524288
#define GG 64
#define NCC 10
#define BNEPS 1e-5f

// ---------------- float scratch arena ----------------------------------------
#define O_B0     0
#define O_BR     (O_B0 + NN*FF)
#define O_X      (O_BR + 3*NN*FF)
#define O_H      (O_X + 3*NN*FF)
#define O_ATT    (O_H + NN*HFD)
#define O_AS     (O_ATT + NN*HFD)
#define O_AD     (O_AS + NN*HH)
#define O_AEX    (O_AD + NN*HH)        // alpha per CSR slot [E,4]
#define O_SALPHA (O_AEX + EGZ*HH)      // self alpha [N,4]
#define O_C0A    (O_SALPHA + NN*HH)    // csr0 attr [E]
#define O_Z      (O_C0A + ESZ)
#define O_XACC   (O_Z + NN*FF)
#define O_STATS  (O_XACC + NN*FF)
#define O_POOL   (O_STATS + 256)
#define O_Y1     (O_POOL + GG*FF)
#define O_Y2     (O_Y1 + GG*256)
#define O_Y3     (O_Y2 + GG*128)
#define ARENA_SZ (O_Y3 + GG*16)

__device__ __align__(256) float g_arena[ARENA_SZ];

// ---------------- int scratch arena -------------------------------------------
#define I_DEGE 0
#define I_CURE (I_DEGE + NN)
#define I_RPE  (I_CURE + NN)
#define I_CSRE (I_RPE + NN)
#define I_DEG0 (I_CSRE + EGZ)
#define I_CUR0 (I_DEG0 + NN)
#define I_RP0  (I_CUR0 + NN)
#define I_CSR0 (I_RP0 + NN)
#define IARENA_SZ (I_CSR0 + ESZ)

__device__ __align__(256) int g_iarena[IARENA_SZ];

// ---------------- helpers -----------------------------------------------------
__device__ __forceinline__ void red4(float* a, float4 v) {
    asm volatile("red.global.add.v4.f32 [%0], {%1,%2,%3,%4};"
                 :: "l"(a), "f"(v.x), "f"(v.y), "f"(v.z), "f"(v.w) : "memory");
}
__device__ __forceinline__ float lrelu(float v) { return v > 0.f ? v : 0.2f * v; }
__device__ __forceinline__ float eluf(float v)  { return v > 0.f ? v : __expf(v) - 1.f; }

// ---------------- CSR build ---------------------------------------------------
__global__ __launch_bounds__(256) void k_hist(const int* __restrict__ dst, int* __restrict__ deg)
{
    int e = blockIdx.x * 256 + threadIdx.x;
    atomicAdd(&deg[dst[e]], 1);
}

// single-block exclusive scan over NN=32768 ints; 256 threads x 128 elems
__global__ __launch_bounds__(256) void k_scan(
    const int* __restrict__ deg, int* __restrict__ rowptr, int* __restrict__ cur)
{
    __shared__ int part[256];
    int t = threadIdx.x;
    int base = t * 128;
    int s = 0;
    for (int i = 0; i < 128; i++) s += deg[base + i];
    part[t] = s;
    __syncthreads();
    for (int off = 1; off < 256; off <<= 1) {
        int v = (t >= off) ? part[t - off] : 0;
        __syncthreads();
        part[t] += v;
        __syncthreads();
    }
    int pre = (t == 0) ? 0 : part[t - 1];
    for (int i = 0; i < 128; i++) {
        rowptr[base + i] = pre;
        cur[base + i] = pre;
        pre += deg[base + i];
    }
}

__global__ __launch_bounds__(256) void k_fillE(
    const int* __restrict__ ei, int* __restrict__ cur, int* __restrict__ csr)
{
    int e = blockIdx.x * 256 + threadIdx.x;
    int d = ei[EGZ + e];
    int p = atomicAdd(&cur[d], 1);
    csr[p] = ei[e];
}

__global__ __launch_bounds__(256) void k_fill0(
    const int* __restrict__ si, const float* __restrict__ sattr,
    int* __restrict__ cur, int* __restrict__ csr, float* __restrict__ csra)
{
    int e = blockIdx.x * 256 + threadIdx.x;
    int d = si[ESZ + e];
    int p = atomicAdd(&cur[d], 1);
    csr[p] = si[e];
    csra[p] = sattr[e];
}

// ---------------- atomic scatter (idx 1..3 raw passes) ------------------------
__global__ __launch_bounds__(256) void k_scatter(
    const int* __restrict__ src, const int* __restrict__ dst,
    const float* __restrict__ attr, const float* __restrict__ xin,
    float* __restrict__ outb)
{
    int t = blockIdx.x * 256 + threadIdx.x;
    int e = t >> 4, lane = t & 15;
    int s = src[e], d = dst[e];
    float a = attr[e];
    float4 v = ((const float4*)xin)[s * 16 + lane];
    v.x *= a; v.y *= a; v.z *= a; v.w *= a;
    red4(outb + d * 64 + lane * 4, v);
}

// CSR gather with idx0: out[n] = sum attr_p * f(x[src_p]); 16 threads/node
__global__ __launch_bounds__(256) void k_gather0(
    const int* __restrict__ rowptr, const int* __restrict__ deg,
    const int* __restrict__ csr, const float* __restrict__ csra,
    const float* __restrict__ xin, float* __restrict__ outb, int doAbs)
{
    int t = blockIdx.x * 256 + threadIdx.x;
    int n = t >> 4, q = t & 15;
    int b = rowptr[n], dg = deg[n];
    float4 acc = make_float4(0.f, 0.f, 0.f, 0.f);
    for (int p = b; p < b + dg; p++) {
        int s = csr[p];
        float a = csra[p];
        float4 v = ((const float4*)xin)[s * 16 + q];
        if (doAbs) { v.x = fabsf(v.x); v.y = fabsf(v.y); v.z = fabsf(v.z); v.w = fabsf(v.w); }
        acc.x += a * v.x; acc.y += a * v.y; acc.z += a * v.z; acc.w += a * v.w;
    }
    ((float4*)outb)[n * 16 + q] = acc;
}

// ---------------- GEMM1: h = xin[N,64] @ W[64,256] ----------------------------
__global__ __launch_bounds__(256) void k_gemm_h(
    const float* __restrict__ xin, const float* __restrict__ W, float* __restrict__ h)
{
    __shared__ float xs[16 * 64];
    int t = threadIdx.x;
    int row0 = blockIdx.x * 16;
    ((float4*)xs)[t] = ((const float4*)(xin + row0 * 64))[t];
    __syncthreads();
    int tx = t & 63, ty = t >> 6;
    float4 acc[4];
    acc[0] = acc[1] = acc[2] = acc[3] = make_float4(0.f, 0.f, 0.f, 0.f);
    const float4* W4 = (const float4*)W;
#pragma unroll 8
    for (int k = 0; k < 64; k++) {
        float4 w = W4[k * 64 + tx];
#pragma unroll
        for (int ri = 0; ri < 4; ri++) {
            float xv = xs[(ty * 4 + ri) * 64 + k];
            acc[ri].x += xv * w.x; acc[ri].y += xv * w.y;
            acc[ri].z += xv * w.z; acc[ri].w += xv * w.w;
        }
    }
#pragma unroll
    for (int ri = 0; ri < 4; ri++)
        ((float4*)h)[(row0 + ty * 4 + ri) * 64 + tx] = acc[ri];
}

// ---------------- attention coefficients a_s, a_d [N,4] -----------------------
__global__ __launch_bounds__(256) void k_attcoef(
    const float* __restrict__ h, const float* __restrict__ asrc,
    const float* __restrict__ adst, float* __restrict__ as_, float* __restrict__ ad_)
{
    int t = blockIdx.x * 256 + threadIdx.x;
    int n = t >> 2, hd = t & 3;
    const float4* h4 = (const float4*)(h + n * 256 + hd * 64);
    const float4* s4 = (const float4*)(asrc + hd * 64);
    const float4* d4 = (const float4*)(adst + hd * 64);
    float ss = 0.f, dd = 0.f;
#pragma unroll
    for (int i = 0; i < 16; i++) {
        float4 hv = h4[i], sv = s4[i], dv = d4[i];
        ss += hv.x * sv.x + hv.y * sv.y + hv.z * sv.z + hv.w * sv.w;
        dd += hv.x * dv.x + hv.y * dv.y + hv.z * dv.z + hv.w * dv.w;
    }
    as_[t] = ss; ad_[t] = dd;
}

// ---------------- fused per-node softmax over CSR (warp/node) -----------------
__global__ __launch_bounds__(256) void k_softmax(
    const int* __restrict__ rowptr, const int* __restrict__ deg, const int* __restrict__ csr,
    const float* __restrict__ as_, const float* __restrict__ ad_,
    float* __restrict__ aex, float* __restrict__ salpha)
{
    int n = blockIdx.x * 8 + (threadIdx.x >> 5);
    int lane = threadIdx.x & 31;
    int b = rowptr[n], dg = deg[n];
    float4 adn = ((const float4*)ad_)[n];
    float4 asn = ((const float4*)as_)[n];
    float4 self;
    self.x = lrelu(asn.x + adn.x); self.y = lrelu(asn.y + adn.y);
    self.z = lrelu(asn.z + adn.z); self.w = lrelu(asn.w + adn.w);

    // pass 1: max
    float4 mx = self;
    for (int j = lane; j < dg; j += 32) {
        float4 sv = ((const float4*)as_)[csr[b + j]];
        mx.x = fmaxf(mx.x, lrelu(sv.x + adn.x));
        mx.y = fmaxf(mx.y, lrelu(sv.y + adn.y));
        mx.z = fmaxf(mx.z, lrelu(sv.z + adn.z));
        mx.w = fmaxf(mx.w, lrelu(sv.w + adn.w));
    }
#pragma unroll
    for (int o = 16; o; o >>= 1) {
        mx.x = fmaxf(mx.x, __shfl_xor_sync(0xffffffffu, mx.x, o));
        mx.y = fmaxf(mx.y, __shfl_xor_sync(0xffffffffu, mx.y, o));
        mx.z = fmaxf(mx.z, __shfl_xor_sync(0xffffffffu, mx.z, o));
        mx.w = fmaxf(mx.w, __shfl_xor_sync(0xffffffffu, mx.w, o));
    }

    // pass 2: exp + sum, store raw exp
    float4 sum = make_float4(0.f, 0.f, 0.f, 0.f);
    for (int j = lane; j < dg; j += 32) {
        float4 sv = ((const float4*)as_)[csr[b + j]];
        float4 ex;
        ex.x = __expf(lrelu(sv.x + adn.x) - mx.x);
        ex.y = __expf(lrelu(sv.y + adn.y) - mx.y);
        ex.z = __expf(lrelu(sv.z + adn.z) - mx.z);
        ex.w = __expf(lrelu(sv.w + adn.w) - mx.w);
        ((float4*)aex)[b + j] = ex;
        sum.x += ex.x; sum.y += ex.y; sum.z += ex.z; sum.w += ex.w;
    }
#pragma unroll
    for (int o = 16; o; o >>= 1) {
        sum.x += __shfl_xor_sync(0xffffffffu, sum.x, o);
        sum.y += __shfl_xor_sync(0xffffffffu, sum.y, o);
        sum.z += __shfl_xor_sync(0xffffffffu, sum.z, o);
        sum.w += __shfl_xor_sync(0xffffffffu, sum.w, o);
    }
    float4 sex;
    sex.x = __expf(self.x - mx.x); sex.y = __expf(self.y - mx.y);
    sex.z = __expf(self.z - mx.z); sex.w = __expf(self.w - mx.w);
    float4 inv;
    inv.x = 1.f / (sum.x + sex.x); inv.y = 1.f / (sum.y + sex.y);
    inv.z = 1.f / (sum.z + sex.z); inv.w = 1.f / (sum.w + sex.w);

    // pass 3: normalize in place
    for (int j = lane; j < dg; j += 32) {
        float4 ex = ((const float4*)aex)[b + j];
        ex.x *= inv.x; ex.y *= inv.y; ex.z *= inv.z; ex.w *= inv.w;
        ((float4*)aex)[b + j] = ex;
    }
    if (lane == 0) {
        float4 sa;
        sa.x = sex.x * inv.x; sa.y = sex.y * inv.y;
        sa.z = sex.z * inv.z; sa.w = sex.w * inv.w;
        ((float4*)salpha)[n] = sa;
    }
}

// ---------------- CSR gather aggregation: 64 threads/node ---------------------
__global__ __launch_bounds__(256) void k_aggr(
    const int* __restrict__ rowptr, const int* __restrict__ deg, const int* __restrict__ csr,
    const float* __restrict__ aex, const float* __restrict__ salpha,
    const float* __restrict__ h, float* __restrict__ att)
{
    int t = blockIdx.x * 256 + threadIdx.x;
    int n = t >> 6, gq = t & 63, hd = gq >> 4;
    int b = rowptr[n], dg = deg[n];
    float a0 = salpha[n * 4 + hd];
    float4 acc = ((const float4*)h)[n * 64 + gq];
    acc.x *= a0; acc.y *= a0; acc.z *= a0; acc.w *= a0;
    for (int p = b; p < b + dg; p++) {
        int s = csr[p];
        float al = aex[p * 4 + hd];
        float4 hv = ((const float4*)h)[s * 64 + gq];
        acc.x += al * hv.x; acc.y += al * hv.y; acc.z += al * hv.z; acc.w += al * hv.w;
    }
    ((float4*)att)[n * 64 + gq] = acc;
}

// ---------------- GEMM2 + fused BN stats --------------------------------------
__global__ __launch_bounds__(256) void k_gemm_z(
    const float* __restrict__ att, const float* __restrict__ bias,
    const float* __restrict__ W, float* __restrict__ z, float* __restrict__ stats)
{
    __shared__ float As[64 * 65];
    __shared__ float red[16][64];
    int t = threadIdx.x;
    int row0 = blockIdx.x * 64;
    int tx = t & 15, ty = t >> 4;
    float4 acc[4];
    acc[0] = acc[1] = acc[2] = acc[3] = make_float4(0.f, 0.f, 0.f, 0.f);
    const float4* W4 = (const float4*)W;
    for (int kc = 0; kc < 4; kc++) {
        __syncthreads();
        for (int i = t; i < 1024; i += 256) {
            int r = i >> 4, c4 = i & 15;
            float4 v = ((const float4*)(att + (row0 + r) * 256 + kc * 64))[c4];
            float4 b = ((const float4*)(bias + kc * 64))[c4];
            float* dp = &As[r * 65 + c4 * 4];
            dp[0] = eluf(v.x + b.x); dp[1] = eluf(v.y + b.y);
            dp[2] = eluf(v.z + b.z); dp[3] = eluf(v.w + b.w);
        }
        __syncthreads();
#pragma unroll 8
        for (int k = 0; k < 64; k++) {
            float4 w = W4[(kc * 64 + k) * 16 + tx];
#pragma unroll
            for (int ri = 0; ri < 4; ri++) {
                float av = As[(ty * 4 + ri) * 65 + k];
                acc[ri].x += av * w.x; acc[ri].y += av * w.y;
                acc[ri].z += av * w.z; acc[ri].w += av * w.w;
            }
        }
    }
#pragma unroll
    for (int ri = 0; ri < 4; ri++)
        ((float4*)z)[(row0 + ty * 4 + ri) * 16 + tx] = acc[ri];

    // fused column stats: sum
    float cs[4];
    cs[0] = acc[0].x + acc[1].x + acc[2].x + acc[3].x;
    cs[1] = acc[0].y + acc[1].y + acc[2].y + acc[3].y;
    cs[2] = acc[0].z + acc[1].z + acc[2].z + acc[3].z;
    cs[3] = acc[0].w + acc[1].w + acc[2].w + acc[3].w;
    __syncthreads();
#pragma unroll
    for (int c = 0; c < 4; c++) red[ty][tx * 4 + c] = cs[c];
    __syncthreads();
    if (t < 64) {
        float s = 0.f;
#pragma unroll
        for (int r = 0; r < 16; r++) s += red[r][t];
        atomicAdd(&stats[t], s);
    }
    // ssq
    cs[0] = acc[0].x*acc[0].x + acc[1].x*acc[1].x + acc[2].x*acc[2].x + acc[3].x*acc[3].x;
    cs[1] = acc[0].y*acc[0].y + acc[1].y*acc[1].y + acc[2].y*acc[2].y + acc[3].y*acc[3].y;
    cs[2] = acc[0].z*acc[0].z + acc[1].z*acc[1].z + acc[2].z*acc[2].z + acc[3].z*acc[3].z;
    cs[3] = acc[0].w*acc[0].w + acc[1].w*acc[1].w + acc[2].w*acc[2].w + acc[3].w*acc[3].w;
    __syncthreads();
#pragma unroll
    for (int c = 0; c < 4; c++) red[ty][tx * 4 + c] = cs[c];
    __syncthreads();
    if (t < 64) {
        float s = 0.f;
#pragma unroll
        for (int r = 0; r < 16; r++) s += red[r][t];
        atomicAdd(&stats[FF + t], s);
    }
}

__global__ void k_finstats(float* stats)
{
    int c = threadIdx.x;
    float mu = stats[c] * (1.f / NN);
    float var = stats[FF + c] * (1.f / NN) - mu * mu;
    stats[128 + c] = mu;
    stats[192 + c] = rsqrtf(var + BNEPS);
}

__global__ __launch_bounds__(256) void k_bnapply(
    const float* __restrict__ z, const float* __restrict__ stats,
    const float* __restrict__ g, const float* __restrict__ be, float* __restrict__ xacc)
{
    int t = blockIdx.x * 256 + threadIdx.x;
    int f = t & 63;
    xacc[t] += (z[t] - stats[128 + f]) * stats[192 + f] * g[f] + be[f];
}

// ---------------- pooling -----------------------------------------------------
__global__ __launch_bounds__(256) void k_pool(
    const float* __restrict__ xacc, const int* __restrict__ batch, float* __restrict__ pool)
{
    int t = blockIdx.x * 256 + threadIdx.x;
    int n = t >> 4, q = t & 15;
    int b = batch[n];
    float4 v = ((const float4*)xacc)[n * 16 + q];
    red4(pool + b * 64 + q * 4, v);
}

// ---------------- FC head -----------------------------------------------------
__global__ __launch_bounds__(256) void k_fc1(
    const float* __restrict__ A, const float* __restrict__ W,
    const float* __restrict__ b, float* __restrict__ Y)
{
    int r = blockIdx.x * 8 + (threadIdx.x >> 5);
    int lane = threadIdx.x & 31;
    const float4* W4 = (const float4*)W;
    float4 acc0 = ((const float4*)b)[lane];
    float4 acc1 = ((const float4*)b)[32 + lane];
#pragma unroll 8
    for (int k = 0; k < 64; k++) {
        float a = __ldg(&A[r * 64 + k]);
        float4 w0 = W4[k * 64 + lane];
        float4 w1 = W4[k * 64 + 32 + lane];
        acc0.x += a * w0.x; acc0.y += a * w0.y; acc0.z += a * w0.z; acc0.w += a * w0.w;
        acc1.x += a * w1.x; acc1.y += a * w1.y; acc1.z += a * w1.z; acc1.w += a * w1.w;
    }
    ((float4*)Y)[r * 64 + lane] = acc0;
    ((float4*)Y)[r * 64 + 32 + lane] = acc1;
}

__global__ __launch_bounds__(256) void k_fc2(
    const float* __restrict__ A, const float* __restrict__ W,
    const float* __restrict__ b, float* __restrict__ Y)
{
    int r = blockIdx.x * 8 + (threadIdx.x >> 5);
    int lane = threadIdx.x & 31;
    const float4* W4 = (const float4*)W;
    float4 acc = ((const float4*)b)[lane];
#pragma unroll 8
    for (int k = 0; k < 256; k++) {
        float a = __ldg(&A[r * 256 + k]);
        float4 w = W4[k * 32 + lane];
        acc.x += a * w.x; acc.y += a * w.y; acc.z += a * w.z; acc.w += a * w.w;
    }
    ((float4*)Y)[r * 32 + lane] = acc;
}

__global__ __launch_bounds__(256) void k_fc3(
    const float* __restrict__ A, const float* __restrict__ W,
    const float* __restrict__ b, float* __restrict__ Y)
{
    int r = blockIdx.x * 8 + (threadIdx.x >> 5);
    int lane = threadIdx.x & 31;
    float acc = (lane < NCC) ? b[lane] : 0.f;
#pragma unroll 8
    for (int k = 0; k < 128; k++) {
        float a = __ldg(&A[r * 128 + k]);
        float w = (lane < NCC) ? W[k * NCC + lane] : 0.f;
        acc += a * w;
    }
    if (lane < NCC) Y[r * NCC + lane] = acc;
}

__global__ void k_bncol(
    const float* __restrict__ Y, float* __restrict__ O, int cols,
    const float* __restrict__ g, const float* __restrict__ be, int relu)
{
    int c = blockIdx.x * blockDim.x + threadIdx.x;
    if (c >= cols) return;
    float s = 0.f, ss = 0.f;
#pragma unroll 8
    for (int r = 0; r < GG; r++) { float v = Y[r * cols + c]; s += v; ss += v * v; }
    float mu = s * (1.f / GG);
    float var = ss * (1.f / GG) - mu * mu;
    float rs = rsqrtf(var + BNEPS);
    float gg = g[c], bb = be[c];
#pragma unroll 8
    for (int r = 0; r < GG; r++) {
        float v = (Y[r * cols + c] - mu) * rs * gg + bb;
        if (relu) v = fmaxf(v, 0.f);
        O[r * cols + c] = v;
    }
}

// ---------------- host orchestration ------------------------------------------
extern "C" void kernel_launch(void* const* d_in, const int* in_sizes, int n_in,
                              void* d_out, int out_size)
{
    const float* x      = (const float*)d_in[0];
    const int*   eidx   = (const int*)d_in[1];
    const int*   batch  = (const int*)d_in[2];
    const int*   sidx   = (const int*)d_in[3];
    const float* sattr  = (const float*)d_in[4];
    const float* gatW   = (const float*)d_in[5];
    const float* gasrc  = (const float*)d_in[6];
    const float* gadst  = (const float*)d_in[7];
    const float* gatb   = (const float*)d_in[8];
    const float* mlpW   = (const float*)d_in[9];
    const float* mlpg   = (const float*)d_in[11];
    const float* mlpbe  = (const float*)d_in[12];
    const float* fc1W   = (const float*)d_in[13];
    const float* fc1b   = (const float*)d_in[14];
    const float* fc1g   = (const float*)d_in[15];
    const float* fc1be  = (const float*)d_in[16];
    const float* fc2W   = (const float*)d_in[17];
    const float* fc2b   = (const float*)d_in[18];
    const float* fc2g   = (const float*)d_in[19];
    const float* fc2be  = (const float*)d_in[20];
    const float* fc3W   = (const float*)d_in[21];
    const float* fc3b   = (const float*)d_in[22];
    const float* fc3g   = (const float*)d_in[23];
    const float* fc3be  = (const float*)d_in[24];
    float* out = (float*)d_out;

    float* A;
    cudaGetSymbolAddress((void**)&A, g_arena);
    int* IA;
    cudaGetSymbolAddress((void**)&IA, g_iarena);

    float* B0     = A + O_B0;
    float* BR     = A + O_BR;
    float* X123   = A + O_X;
    float* H      = A + O_H;
    float* ATT    = A + O_ATT;
    float* AS     = A + O_AS;
    float* AD     = A + O_AD;
    float* AEX    = A + O_AEX;
    float* SALPHA = A + O_SALPHA;
    float* C0A    = A + O_C0A;
    float* Z      = A + O_Z;
    float* XACC   = A + O_XACC;
    float* ST     = A + O_STATS;
    float* POOL   = A + O_POOL;
    float* Y1     = A + O_Y1;
    float* Y2     = A + O_Y2;
    float* Y3     = A + O_Y3;

    int* DEGE = IA + I_DEGE;
    int* CURE = IA + I_CURE;
    int* RPE  = IA + I_RPE;
    int* CSRE = IA + I_CSRE;
    int* DEG0 = IA + I_DEG0;
    int* CUR0 = IA + I_CUR0;
    int* RP0  = IA + I_RP0;
    int* CSR0 = IA + I_CSR0;

    // ---- CSR builds ----
    cudaMemsetAsync(DEGE, 0, NN * sizeof(int));
    cudaMemsetAsync(DEG0, 0, NN * sizeof(int));
    k_hist<<<EGZ / 256, 256>>>(eidx + EGZ, DEGE);
    k_hist<<<ESZ / 256, 256>>>(sidx + ESZ, DEG0);
    k_scan<<<1, 256>>>(DEGE, RPE, CURE);
    k_scan<<<1, 256>>>(DEG0, RP0, CUR0);
    k_fillE<<<EGZ / 256, 256>>>(eidx, CURE, CSRE);
    k_fill0<<<ESZ / 256, 256>>>(sidx, sattr, CUR0, CSR0, C0A);

    // ---- scatter stage ----
    cudaMemsetAsync(BR, 0, (size_t)3 * NN * FF * sizeof(float));
    const int SGRID = ESZ * 16 / 256;
    for (int j = 1; j <= 3; j++)
        k_scatter<<<SGRID, 256>>>(sidx + j * 2 * ESZ, sidx + j * 2 * ESZ + ESZ,
                                  sattr + j * ESZ, x, BR + (j - 1) * NN * FF);
    k_gather0<<<NN * 16 / 256, 256>>>(RP0, DEG0, CSR0, C0A, x, B0, 0);
    for (int j = 1; j <= 3; j++)
        k_gather0<<<NN * 16 / 256, 256>>>(RP0, DEG0, CSR0, C0A,
                                          BR + (j - 1) * NN * FF, X123 + (j - 1) * NN * FF, 1);

    cudaMemcpyAsync(XACC, x, (size_t)NN * FF * sizeof(float), cudaMemcpyDeviceToDevice);

    const float* bx[4] = { B0, X123, X123 + NN * FF, X123 + 2 * NN * FF };

    // ---- 4 GAT branches ----
    for (int br = 0; br < 4; br++) {
        k_gemm_h<<<NN / 16, 256>>>(bx[br], gatW + br * FF * HFD, H);
        k_attcoef<<<NN * HH / 256, 256>>>(H, gasrc + br * HH * FF, gadst + br * HH * FF, AS, AD);
        k_softmax<<<NN / 8, 256>>>(RPE, DEGE, CSRE, AS, AD, AEX, SALPHA);
        k_aggr<<<NN * 64 / 256, 256>>>(RPE, DEGE, CSRE, AEX, SALPHA, H, ATT);
        cudaMemsetAsync(ST, 0, 128 * sizeof(float));
        k_gemm_z<<<NN / 64, 256>>>(ATT, gatb + br * HFD, mlpW + br * HFD * FF, Z, ST);
        k_finstats<<<1, 64>>>(ST);
        k_bnapply<<<NN * FF / 256, 256>>>(Z, ST, mlpg + br * FF, mlpbe + br * FF, XACC);
    }

    // ---- pooling + head ----
    cudaMemsetAsync(POOL, 0, (size_t)GG * FF * sizeof(float));
    k_pool<<<NN * 16 / 256, 256>>>(XACC, batch, POOL);

    k_fc1<<<8, 256>>>(POOL, fc1W, fc1b, Y1);
    k_bncol<<<1, 256>>>(Y1, Y1, 256, fc1g, fc1be, 1);
    k_fc2<<<8, 256>>>(Y1, fc2W, fc2b, Y2);
    k_bncol<<<1, 128>>>(Y2, Y2, 128, fc2g, fc2be, 1);
    k_fc3<<<8, 256>>>(Y2, fc3W, fc3b, Y3);
    k_bncol<<<1, 32>>>(Y3, out, NCC, fc3g, fc3be, 0);
}

// round 5
// speedup vs baseline: 1.4736x; 1.1185x over previous
#include <cuda_runtime.h>
#include <math.h>

#define NN 32768
#define FF 64
#define HH 4
#define HFD 256
#define ESZ 524288
#define EGZ 524288
#define GG 64
#define NCC 10
#define BNEPS 1e-5f

// ---------------- float scratch arena ----------------------------------------
#define O_B0     0
#define O_BR     (O_B0 + NN*FF)
#define O_X      (O_BR + 3*NN*FF)
#define O_H      (O_X + 3*NN*FF)
#define O_ATT    (O_H + NN*HFD)
#define O_AS     (O_ATT + NN*HFD)
#define O_AD     (O_AS + NN*HH)
#define O_AEX    (O_AD + NN*HH)        // alpha per CSR slot [E,4]
#define O_SALPHA (O_AEX + EGZ*HH)      // self alpha [N,4]
#define O_C0A    (O_SALPHA + NN*HH)    // csr0 attr [E]
#define O_Z      (O_C0A + ESZ)
#define O_XACC   (O_Z + NN*FF)
#define O_STATS  (O_XACC + NN*FF)
#define O_POOL   (O_STATS + 256)
#define O_Y1     (O_POOL + GG*FF)
#define O_Y2     (O_Y1 + GG*256)
#define O_Y3     (O_Y2 + GG*128)
#define ARENA_SZ (O_Y3 + GG*16)

__device__ __align__(256) float g_arena[ARENA_SZ];

// ---------------- int scratch arena -------------------------------------------
#define I_DEGE 0
#define I_CURE (I_DEGE + NN)
#define I_RPE  (I_CURE + NN)
#define I_CSRE (I_RPE + NN)
#define I_DEG0 (I_CSRE + EGZ)
#define I_CUR0 (I_DEG0 + NN)
#define I_RP0  (I_CUR0 + NN)
#define I_CSR0 (I_RP0 + NN)
#define I_BSUM (I_CSR0 + ESZ)          // 128 block partials
#define IARENA_SZ (I_BSUM + 128)

__device__ __align__(256) int g_iarena[IARENA_SZ];

// ---------------- helpers -----------------------------------------------------
__device__ __forceinline__ void red4(float* a, float4 v) {
    asm volatile("red.global.add.v4.f32 [%0], {%1,%2,%3,%4};"
                 :: "l"(a), "f"(v.x), "f"(v.y), "f"(v.z), "f"(v.w) : "memory");
}
__device__ __forceinline__ float lrelu(float v) { return v > 0.f ? v : 0.2f * v; }
__device__ __forceinline__ float eluf(float v)  { return v > 0.f ? v : __expf(v) - 1.f; }

// ---------------- CSR build ---------------------------------------------------
__global__ __launch_bounds__(256) void k_hist(const int* __restrict__ dst, int* __restrict__ deg)
{
    int e = blockIdx.x * 256 + threadIdx.x;
    atomicAdd(&deg[dst[e]], 1);
}

// phase 1: per-block sums of 256-element chunks  (grid = NN/256 = 128)
__global__ __launch_bounds__(256) void k_blocksum(
    const int* __restrict__ deg, int* __restrict__ bsum)
{
    __shared__ int sh[256];
    int t = threadIdx.x;
    int v = deg[blockIdx.x * 256 + t];
    sh[t] = v;
    __syncthreads();
#pragma unroll
    for (int off = 128; off; off >>= 1) {
        if (t < off) sh[t] += sh[t + off];
        __syncthreads();
    }
    if (t == 0) bsum[blockIdx.x] = sh[0];
}

// phase 2: exclusive scan of 128 partials (1 block, 128 thr)
__global__ __launch_bounds__(128) void k_scanbs(int* __restrict__ bsum)
{
    __shared__ int sh[128];
    int t = threadIdx.x;
    int v = bsum[t];
    sh[t] = v;
    __syncthreads();
#pragma unroll
    for (int off = 1; off < 128; off <<= 1) {
        int u = (t >= off) ? sh[t - off] : 0;
        __syncthreads();
        sh[t] += u;
        __syncthreads();
    }
    bsum[t] = sh[t] - v;   // exclusive
}

// phase 3: per-chunk exclusive scan + block offset; writes rowptr & cur
__global__ __launch_bounds__(256) void k_scanout(
    const int* __restrict__ deg, const int* __restrict__ bsum,
    int* __restrict__ rowptr, int* __restrict__ cur)
{
    __shared__ int sh[256];
    int t = threadIdx.x;
    int g = blockIdx.x * 256 + t;
    int v = deg[g];
    sh[t] = v;
    __syncthreads();
#pragma unroll
    for (int off = 1; off < 256; off <<= 1) {
        int u = (t >= off) ? sh[t - off] : 0;
        __syncthreads();
        sh[t] += u;
        __syncthreads();
    }
    int ex = sh[t] - v + bsum[blockIdx.x];
    rowptr[g] = ex;
    cur[g] = ex;
}

__global__ __launch_bounds__(256) void k_fillE(
    const int* __restrict__ ei, int* __restrict__ cur, int* __restrict__ csr)
{
    int e = blockIdx.x * 256 + threadIdx.x;
    int d = ei[EGZ + e];
    int p = atomicAdd(&cur[d], 1);
    csr[p] = ei[e];
}

__global__ __launch_bounds__(256) void k_fill0(
    const int* __restrict__ si, const float* __restrict__ sattr,
    int* __restrict__ cur, int* __restrict__ csr, float* __restrict__ csra)
{
    int e = blockIdx.x * 256 + threadIdx.x;
    int d = si[ESZ + e];
    int p = atomicAdd(&cur[d], 1);
    csr[p] = si[e];
    csra[p] = sattr[e];
}

// ---------------- atomic scatter (idx 1..3 raw passes) ------------------------
__global__ __launch_bounds__(256) void k_scatter(
    const int* __restrict__ src, const int* __restrict__ dst,
    const float* __restrict__ attr, const float* __restrict__ xin,
    float* __restrict__ outb)
{
    int t = blockIdx.x * 256 + threadIdx.x;
    int e = t >> 4, lane = t & 15;
    int s = src[e], d = dst[e];
    float a = attr[e];
    float4 v = ((const float4*)xin)[s * 16 + lane];
    v.x *= a; v.y *= a; v.z *= a; v.w *= a;
    red4(outb + d * 64 + lane * 4, v);
}

// CSR gather with idx0: out[n] = sum attr_p * f(x[src_p]); 16 threads/node
__global__ __launch_bounds__(256) void k_gather0(
    const int* __restrict__ rowptr, const int* __restrict__ deg,
    const int* __restrict__ csr, const float* __restrict__ csra,
    const float* __restrict__ xin, float* __restrict__ outb, int doAbs)
{
    int t = blockIdx.x * 256 + threadIdx.x;
    int n = t >> 4, q = t & 15;
    int b = rowptr[n], dg = deg[n];
    float4 acc = make_float4(0.f, 0.f, 0.f, 0.f);
    for (int p = b; p < b + dg; p++) {
        int s = csr[p];
        float a = csra[p];
        float4 v = ((const float4*)xin)[s * 16 + q];
        if (doAbs) { v.x = fabsf(v.x); v.y = fabsf(v.y); v.z = fabsf(v.z); v.w = fabsf(v.w); }
        acc.x += a * v.x; acc.y += a * v.y; acc.z += a * v.z; acc.w += a * v.w;
    }
    ((float4*)outb)[n * 16 + q] = acc;
}

// ---------------- GEMM1: h = xin[N,64] @ W[64,256] ----------------------------
__global__ __launch_bounds__(256) void k_gemm_h(
    const float* __restrict__ xin, const float* __restrict__ W, float* __restrict__ h)
{
    __shared__ float xs[16 * 64];
    int t = threadIdx.x;
    int row0 = blockIdx.x * 16;
    ((float4*)xs)[t] = ((const float4*)(xin + row0 * 64))[t];
    __syncthreads();
    int tx = t & 63, ty = t >> 6;
    float4 acc[4];
    acc[0] = acc[1] = acc[2] = acc[3] = make_float4(0.f, 0.f, 0.f, 0.f);
    const float4* W4 = (const float4*)W;
#pragma unroll 8
    for (int k = 0; k < 64; k++) {
        float4 w = W4[k * 64 + tx];
#pragma unroll
        for (int ri = 0; ri < 4; ri++) {
            float xv = xs[(ty * 4 + ri) * 64 + k];
            acc[ri].x += xv * w.x; acc[ri].y += xv * w.y;
            acc[ri].z += xv * w.z; acc[ri].w += xv * w.w;
        }
    }
#pragma unroll
    for (int ri = 0; ri < 4; ri++)
        ((float4*)h)[(row0 + ty * 4 + ri) * 64 + tx] = acc[ri];
}

// ---------------- attention coefficients a_s, a_d [N,4] -----------------------
__global__ __launch_bounds__(256) void k_attcoef(
    const float* __restrict__ h, const float* __restrict__ asrc,
    const float* __restrict__ adst, float* __restrict__ as_, float* __restrict__ ad_)
{
    int t = blockIdx.x * 256 + threadIdx.x;
    int n = t >> 2, hd = t & 3;
    const float4* h4 = (const float4*)(h + n * 256 + hd * 64);
    const float4* s4 = (const float4*)(asrc + hd * 64);
    const float4* d4 = (const float4*)(adst + hd * 64);
    float ss = 0.f, dd = 0.f;
#pragma unroll
    for (int i = 0; i < 16; i++) {
        float4 hv = h4[i], sv = s4[i], dv = d4[i];
        ss += hv.x * sv.x + hv.y * sv.y + hv.z * sv.z + hv.w * sv.w;
        dd += hv.x * dv.x + hv.y * dv.y + hv.z * dv.z + hv.w * dv.w;
    }
    as_[t] = ss; ad_[t] = dd;
}

// ---------------- fused per-node softmax over CSR (warp/node) -----------------
__global__ __launch_bounds__(256) void k_softmax(
    const int* __restrict__ rowptr, const int* __restrict__ deg, const int* __restrict__ csr,
    const float* __restrict__ as_, const float* __restrict__ ad_,
    float* __restrict__ aex, float* __restrict__ salpha)
{
    int n = blockIdx.x * 8 + (threadIdx.x >> 5);
    int lane = threadIdx.x & 31;
    int b = rowptr[n], dg = deg[n];
    float4 adn = ((const float4*)ad_)[n];
    float4 asn = ((const float4*)as_)[n];
    float4 self;
    self.x = lrelu(asn.x + adn.x); self.y = lrelu(asn.y + adn.y);
    self.z = lrelu(asn.z + adn.z); self.w = lrelu(asn.w + adn.w);

    // pass 1: max
    float4 mx = self;
    for (int j = lane; j < dg; j += 32) {
        float4 sv = ((const float4*)as_)[csr[b + j]];
        mx.x = fmaxf(mx.x, lrelu(sv.x + adn.x));
        mx.y = fmaxf(mx.y, lrelu(sv.y + adn.y));
        mx.z = fmaxf(mx.z, lrelu(sv.z + adn.z));
        mx.w = fmaxf(mx.w, lrelu(sv.w + adn.w));
    }
#pragma unroll
    for (int o = 16; o; o >>= 1) {
        mx.x = fmaxf(mx.x, __shfl_xor_sync(0xffffffffu, mx.x, o));
        mx.y = fmaxf(mx.y, __shfl_xor_sync(0xffffffffu, mx.y, o));
        mx.z = fmaxf(mx.z, __shfl_xor_sync(0xffffffffu, mx.z, o));
        mx.w = fmaxf(mx.w, __shfl_xor_sync(0xffffffffu, mx.w, o));
    }

    // pass 2: exp + sum, store raw exp
    float4 sum = make_float4(0.f, 0.f, 0.f, 0.f);
    for (int j = lane; j < dg; j += 32) {
        float4 sv = ((const float4*)as_)[csr[b + j]];
        float4 ex;
        ex.x = __expf(lrelu(sv.x + adn.x) - mx.x);
        ex.y = __expf(lrelu(sv.y + adn.y) - mx.y);
        ex.z = __expf(lrelu(sv.z + adn.z) - mx.z);
        ex.w = __expf(lrelu(sv.w + adn.w) - mx.w);
        ((float4*)aex)[b + j] = ex;
        sum.x += ex.x; sum.y += ex.y; sum.z += ex.z; sum.w += ex.w;
    }
#pragma unroll
    for (int o = 16; o; o >>= 1) {
        sum.x += __shfl_xor_sync(0xffffffffu, sum.x, o);
        sum.y += __shfl_xor_sync(0xffffffffu, sum.y, o);
        sum.z += __shfl_xor_sync(0xffffffffu, sum.z, o);
        sum.w += __shfl_xor_sync(0xffffffffu, sum.w, o);
    }
    float4 sex;
    sex.x = __expf(self.x - mx.x); sex.y = __expf(self.y - mx.y);
    sex.z = __expf(self.z - mx.z); sex.w = __expf(self.w - mx.w);
    float4 inv;
    inv.x = 1.f / (sum.x + sex.x); inv.y = 1.f / (sum.y + sex.y);
    inv.z = 1.f / (sum.z + sex.z); inv.w = 1.f / (sum.w + sex.w);

    // pass 3: normalize in place
    for (int j = lane; j < dg; j += 32) {
        float4 ex = ((const float4*)aex)[b + j];
        ex.x *= inv.x; ex.y *= inv.y; ex.z *= inv.z; ex.w *= inv.w;
        ((float4*)aex)[b + j] = ex;
    }
    if (lane == 0) {
        float4 sa;
        sa.x = sex.x * inv.x; sa.y = sex.y * inv.y;
        sa.z = sex.z * inv.z; sa.w = sex.w * inv.w;
        ((float4*)salpha)[n] = sa;
    }
}

// ---------------- CSR gather aggregation: 64 threads/node ---------------------
__global__ __launch_bounds__(256) void k_aggr(
    const int* __restrict__ rowptr, const int* __restrict__ deg, const int* __restrict__ csr,
    const float* __restrict__ aex, const float* __restrict__ salpha,
    const float* __restrict__ h, float* __restrict__ att)
{
    int t = blockIdx.x * 256 + threadIdx.x;
    int n = t >> 6, gq = t & 63, hd = gq >> 4;
    int b = rowptr[n], dg = deg[n];
    float a0 = salpha[n * 4 + hd];
    float4 acc = ((const float4*)h)[n * 64 + gq];
    acc.x *= a0; acc.y *= a0; acc.z *= a0; acc.w *= a0;
    for (int p = b; p < b + dg; p++) {
        int s = csr[p];
        float al = aex[p * 4 + hd];
        float4 hv = ((const float4*)h)[s * 64 + gq];
        acc.x += al * hv.x; acc.y += al * hv.y; acc.z += al * hv.z; acc.w += al * hv.w;
    }
    ((float4*)att)[n * 64 + gq] = acc;
}

// ---------------- GEMM2 + fused BN stats --------------------------------------
__global__ __launch_bounds__(256) void k_gemm_z(
    const float* __restrict__ att, const float* __restrict__ bias,
    const float* __restrict__ W, float* __restrict__ z, float* __restrict__ stats)
{
    __shared__ float As[64 * 65];
    __shared__ float red[16][64];
    int t = threadIdx.x;
    int row0 = blockIdx.x * 64;
    int tx = t & 15, ty = t >> 4;
    float4 acc[4];
    acc[0] = acc[1] = acc[2] = acc[3] = make_float4(0.f, 0.f, 0.f, 0.f);
    const float4* W4 = (const float4*)W;
    for (int kc = 0; kc < 4; kc++) {
        __syncthreads();
        for (int i = t; i < 1024; i += 256) {
            int r = i >> 4, c4 = i & 15;
            float4 v = ((const float4*)(att + (row0 + r) * 256 + kc * 64))[c4];
            float4 b = ((const float4*)(bias + kc * 64))[c4];
            float* dp = &As[r * 65 + c4 * 4];
            dp[0] = eluf(v.x + b.x); dp[1] = eluf(v.y + b.y);
            dp[2] = eluf(v.z + b.z); dp[3] = eluf(v.w + b.w);
        }
        __syncthreads();
#pragma unroll 8
        for (int k = 0; k < 64; k++) {
            float4 w = W4[(kc * 64 + k) * 16 + tx];
#pragma unroll
            for (int ri = 0; ri < 4; ri++) {
                float av = As[(ty * 4 + ri) * 65 + k];
                acc[ri].x += av * w.x; acc[ri].y += av * w.y;
                acc[ri].z += av * w.z; acc[ri].w += av * w.w;
            }
        }
    }
#pragma unroll
    for (int ri = 0; ri < 4; ri++)
        ((float4*)z)[(row0 + ty * 4 + ri) * 16 + tx] = acc[ri];

    // fused column stats: sum
    float cs[4];
    cs[0] = acc[0].x + acc[1].x + acc[2].x + acc[3].x;
    cs[1] = acc[0].y + acc[1].y + acc[2].y + acc[3].y;
    cs[2] = acc[0].z + acc[1].z + acc[2].z + acc[3].z;
    cs[3] = acc[0].w + acc[1].w + acc[2].w + acc[3].w;
    __syncthreads();
#pragma unroll
    for (int c = 0; c < 4; c++) red[ty][tx * 4 + c] = cs[c];
    __syncthreads();
    if (t < 64) {
        float s = 0.f;
#pragma unroll
        for (int r = 0; r < 16; r++) s += red[r][t];
        atomicAdd(&stats[t], s);
    }
    // ssq
    cs[0] = acc[0].x*acc[0].x + acc[1].x*acc[1].x + acc[2].x*acc[2].x + acc[3].x*acc[3].x;
    cs[1] = acc[0].y*acc[0].y + acc[1].y*acc[1].y + acc[2].y*acc[2].y + acc[3].y*acc[3].y;
    cs[2] = acc[0].z*acc[0].z + acc[1].z*acc[1].z + acc[2].z*acc[2].z + acc[3].z*acc[3].z;
    cs[3] = acc[0].w*acc[0].w + acc[1].w*acc[1].w + acc[2].w*acc[2].w + acc[3].w*acc[3].w;
    __syncthreads();
#pragma unroll
    for (int c = 0; c < 4; c++) red[ty][tx * 4 + c] = cs[c];
    __syncthreads();
    if (t < 64) {
        float s = 0.f;
#pragma unroll
        for (int r = 0; r < 16; r++) s += red[r][t];
        atomicAdd(&stats[FF + t], s);
    }
}

__global__ void k_finstats(float* stats)
{
    int c = threadIdx.x;
    float mu = stats[c] * (1.f / NN);
    float var = stats[FF + c] * (1.f / NN) - mu * mu;
    stats[128 + c] = mu;
    stats[192 + c] = rsqrtf(var + BNEPS);
}

__global__ __launch_bounds__(256) void k_bnapply(
    const float* __restrict__ z, const float* __restrict__ stats,
    const float* __restrict__ g, const float* __restrict__ be, float* __restrict__ xacc)
{
    int t = blockIdx.x * 256 + threadIdx.x;
    int f = t & 63;
    xacc[t] += (z[t] - stats[128 + f]) * stats[192 + f] * g[f] + be[f];
}

// ---------------- pooling -----------------------------------------------------
__global__ __launch_bounds__(256) void k_pool(
    const float* __restrict__ xacc, const int* __restrict__ batch, float* __restrict__ pool)
{
    int t = blockIdx.x * 256 + threadIdx.x;
    int n = t >> 4, q = t & 15;
    int b = batch[n];
    float4 v = ((const float4*)xacc)[n * 16 + q];
    red4(pool + b * 64 + q * 4, v);
}

// ---------------- FC head -----------------------------------------------------
__global__ __launch_bounds__(256) void k_fc1(
    const float* __restrict__ A, const float* __restrict__ W,
    const float* __restrict__ b, float* __restrict__ Y)
{
    int r = blockIdx.x * 8 + (threadIdx.x >> 5);
    int lane = threadIdx.x & 31;
    const float4* W4 = (const float4*)W;
    float4 acc0 = ((const float4*)b)[lane];
    float4 acc1 = ((const float4*)b)[32 + lane];
#pragma unroll 8
    for (int k = 0; k < 64; k++) {
        float a = __ldg(&A[r * 64 + k]);
        float4 w0 = W4[k * 64 + lane];
        float4 w1 = W4[k * 64 + 32 + lane];
        acc0.x += a * w0.x; acc0.y += a * w0.y; acc0.z += a * w0.z; acc0.w += a * w0.w;
        acc1.x += a * w1.x; acc1.y += a * w1.y; acc1.z += a * w1.z; acc1.w += a * w1.w;
    }
    ((float4*)Y)[r * 64 + lane] = acc0;
    ((float4*)Y)[r * 64 + 32 + lane] = acc1;
}

__global__ __launch_bounds__(256) void k_fc2(
    const float* __restrict__ A, const float* __restrict__ W,
    const float* __restrict__ b, float* __restrict__ Y)
{
    int r = blockIdx.x * 8 + (threadIdx.x >> 5);
    int lane = threadIdx.x & 31;
    const float4* W4 = (const float4*)W;
    float4 acc = ((const float4*)b)[lane];
#pragma unroll 8
    for (int k = 0; k < 256; k++) {
        float a = __ldg(&A[r * 256 + k]);
        float4 w = W4[k * 32 + lane];
        acc.x += a * w.x; acc.y += a * w.y; acc.z += a * w.z; acc.w += a * w.w;
    }
    ((float4*)Y)[r * 32 + lane] = acc;
}

__global__ __launch_bounds__(256) void k_fc3(
    const float* __restrict__ A, const float* __restrict__ W,
    const float* __restrict__ b, float* __restrict__ Y)
{
    int r = blockIdx.x * 8 + (threadIdx.x >> 5);
    int lane = threadIdx.x & 31;
    float acc = (lane < NCC) ? b[lane] : 0.f;
#pragma unroll 8
    for (int k = 0; k < 128; k++) {
        float a = __ldg(&A[r * 128 + k]);
        float w = (lane < NCC) ? W[k * NCC + lane] : 0.f;
        acc += a * w;
    }
    if (lane < NCC) Y[r * NCC + lane] = acc;
}

__global__ void k_bncol(
    const float* __restrict__ Y, float* __restrict__ O, int cols,
    const float* __restrict__ g, const float* __restrict__ be, int relu)
{
    int c = blockIdx.x * blockDim.x + threadIdx.x;
    if (c >= cols) return;
    float s = 0.f, ss = 0.f;
#pragma unroll 8
    for (int r = 0; r < GG; r++) { float v = Y[r * cols + c]; s += v; ss += v * v; }
    float mu = s * (1.f / GG);
    float var = ss * (1.f / GG) - mu * mu;
    float rs = rsqrtf(var + BNEPS);
    float gg = g[c], bb = be[c];
#pragma unroll 8
    for (int r = 0; r < GG; r++) {
        float v = (Y[r * cols + c] - mu) * rs * gg + bb;
        if (relu) v = fmaxf(v, 0.f);
        O[r * cols + c] = v;
    }
}

// ---------------- host orchestration ------------------------------------------
extern "C" void kernel_launch(void* const* d_in, const int* in_sizes, int n_in,
                              void* d_out, int out_size)
{
    const float* x      = (const float*)d_in[0];
    const int*   eidx   = (const int*)d_in[1];
    const int*   batch  = (const int*)d_in[2];
    const int*   sidx   = (const int*)d_in[3];
    const float* sattr  = (const float*)d_in[4];
    const float* gatW   = (const float*)d_in[5];
    const float* gasrc  = (const float*)d_in[6];
    const float* gadst  = (const float*)d_in[7];
    const float* gatb   = (const float*)d_in[8];
    const float* mlpW   = (const float*)d_in[9];
    const float* mlpg   = (const float*)d_in[11];
    const float* mlpbe  = (const float*)d_in[12];
    const float* fc1W   = (const float*)d_in[13];
    const float* fc1b   = (const float*)d_in[14];
    const float* fc1g   = (const float*)d_in[15];
    const float* fc1be  = (const float*)d_in[16];
    const float* fc2W   = (const float*)d_in[17];
    const float* fc2b   = (const float*)d_in[18];
    const float* fc2g   = (const float*)d_in[19];
    const float* fc2be  = (const float*)d_in[20];
    const float* fc3W   = (const float*)d_in[21];
    const float* fc3b   = (const float*)d_in[22];
    const float* fc3g   = (const float*)d_in[23];
    const float* fc3be  = (const float*)d_in[24];
    float* out = (float*)d_out;

    float* A;
    cudaGetSymbolAddress((void**)&A, g_arena);
    int* IA;
    cudaGetSymbolAddress((void**)&IA, g_iarena);

    float* B0     = A + O_B0;
    float* BR     = A + O_BR;
    float* X123   = A + O_X;
    float* H      = A + O_H;
    float* ATT    = A + O_ATT;
    float* AS     = A + O_AS;
    float* AD     = A + O_AD;
    float* AEX    = A + O_AEX;
    float* SALPHA = A + O_SALPHA;
    float* C0A    = A + O_C0A;
    float* Z      = A + O_Z;
    float* XACC   = A + O_XACC;
    float* ST     = A + O_STATS;
    float* POOL   = A + O_POOL;
    float* Y1     = A + O_Y1;
    float* Y2     = A + O_Y2;
    float* Y3     = A + O_Y3;

    int* DEGE = IA + I_DEGE;
    int* CURE = IA + I_CURE;
    int* RPE  = IA + I_RPE;
    int* CSRE = IA + I_CSRE;
    int* DEG0 = IA + I_DEG0;
    int* CUR0 = IA + I_CUR0;
    int* RP0  = IA + I_RP0;
    int* CSR0 = IA + I_CSR0;
    int* BSUM = IA + I_BSUM;

    // ---- CSR builds (multi-block scan) ----
    cudaMemsetAsync(DEGE, 0, NN * sizeof(int));
    cudaMemsetAsync(DEG0, 0, NN * sizeof(int));
    k_hist<<<EGZ / 256, 256>>>(eidx + EGZ, DEGE);
    k_hist<<<ESZ / 256, 256>>>(sidx + ESZ, DEG0);
    k_blocksum<<<NN / 256, 256>>>(DEGE, BSUM);
    k_scanbs<<<1, 128>>>(BSUM);
    k_scanout<<<NN / 256, 256>>>(DEGE, BSUM, RPE, CURE);
    k_fillE<<<EGZ / 256, 256>>>(eidx, CURE, CSRE);
    k_blocksum<<<NN / 256, 256>>>(DEG0, BSUM);
    k_scanbs<<<1, 128>>>(BSUM);
    k_scanout<<<NN / 256, 256>>>(DEG0, BSUM, RP0, CUR0);
    k_fill0<<<ESZ / 256, 256>>>(sidx, sattr, CUR0, CSR0, C0A);

    // ---- scatter stage ----
    cudaMemsetAsync(BR, 0, (size_t)3 * NN * FF * sizeof(float));
    const int SGRID = ESZ * 16 / 256;
    for (int j = 1; j <= 3; j++)
        k_scatter<<<SGRID, 256>>>(sidx + j * 2 * ESZ, sidx + j * 2 * ESZ + ESZ,
                                  sattr + j * ESZ, x, BR + (j - 1) * NN * FF);
    k_gather0<<<NN * 16 / 256, 256>>>(RP0, DEG0, CSR0, C0A, x, B0, 0);
    for (int j = 1; j <= 3; j++)
        k_gather0<<<NN * 16 / 256, 256>>>(RP0, DEG0, CSR0, C0A,
                                          BR + (j - 1) * NN * FF, X123 + (j - 1) * NN * FF, 1);

    cudaMemcpyAsync(XACC, x, (size_t)NN * FF * sizeof(float), cudaMemcpyDeviceToDevice);

    const float* bx[4] = { B0, X123, X123 + NN * FF, X123 + 2 * NN * FF };

    // ---- 4 GAT branches ----
    for (int br = 0; br < 4; br++) {
        k_gemm_h<<<NN / 16, 256>>>(bx[br], gatW + br * FF * HFD, H);
        k_attcoef<<<NN * HH / 256, 256>>>(H, gasrc + br * HH * FF, gadst + br * HH * FF, AS, AD);
        k_softmax<<<NN / 8, 256>>>(RPE, DEGE, CSRE, AS, AD, AEX, SALPHA);
        k_aggr<<<NN * 64 / 256, 256>>>(RPE, DEGE, CSRE, AEX, SALPHA, H, ATT);
        cudaMemsetAsync(ST, 0, 128 * sizeof(float));
        k_gemm_z<<<NN / 64, 256>>>(ATT, gatb + br * HFD, mlpW + br * HFD * FF, Z, ST);
        k_finstats<<<1, 64>>>(ST);
        k_bnapply<<<NN * FF / 256, 256>>>(Z, ST, mlpg + br * FF, mlpbe + br * FF, XACC);
    }

    // ---- pooling + head ----
    cudaMemsetAsync(POOL, 0, (size_t)GG * FF * sizeof(float));
    k_pool<<<NN * 16 / 256, 256>>>(XACC, batch, POOL);

    k_fc1<<<8, 256>>>(POOL, fc1W, fc1b, Y1);
    k_bncol<<<1, 256>>>(Y1, Y1, 256, fc1g, fc1be, 1);
    k_fc2<<<8, 256>>>(Y1, fc2W, fc2b, Y2);
    k_bncol<<<1, 128>>>(Y2, Y2, 128, fc2g, fc2be, 1);
    k_fc3<<<8, 256>>>(Y2, fc3W, fc3b, Y3);
    k_bncol<<<1, 32>>>(Y3, out, NCC, fc3g, fc3be, 0);
}

// round 6
// speedup vs baseline: 1.5763x; 1.0697x over previous
#include <cuda_runtime.h>
#include <math.h>

#define NN 32768
#define FF 64
#define HH 4
#define HFD 256
#define ESZ 524288
#define EGZ 524288
#define GG 64
#define NCC 10
#define BNEPS 1e-5f

// ---------------- float scratch arena ----------------------------------------
#define O_B0     0
#define O_BR     (O_B0 + NN*FF)
#define O_X      (O_BR + 3*NN*FF)
#define O_H      (O_X + 3*NN*FF)
#define O_ATT    (O_H + NN*HFD)
#define O_AS     (O_ATT + NN*HFD)
#define O_AD     (O_AS + NN*HH)
#define O_AEX    (O_AD + NN*HH)        // raw exp per CSR slot [E,4]
#define O_SEXP   (O_AEX + EGZ*HH)      // self exp [N,4]
#define O_INV    (O_SEXP + NN*HH)      // 1/denom [N,4]
#define O_C0A    (O_INV + NN*HH)       // csr0 attr [E]
#define O_Z      (O_C0A + ESZ)
#define O_XACC   (O_Z + NN*FF)
#define O_STATS  (O_XACC + NN*FF)      // 4 branches x 128 floats
#define O_POOL   (O_STATS + 512)
#define ARENA_SZ (O_POOL + GG*FF)

__device__ __align__(256) float g_arena[ARENA_SZ];

// ---------------- int scratch arena -------------------------------------------
#define I_DEGE 0
#define I_CURE (I_DEGE + NN)
#define I_RPE  (I_CURE + NN)
#define I_CSRE (I_RPE + NN)
#define I_DEG0 (I_CSRE + EGZ)
#define I_CUR0 (I_DEG0 + NN)
#define I_RP0  (I_CUR0 + NN)
#define I_CSR0 (I_RP0 + NN)
#define I_BSUM (I_CSR0 + ESZ)
#define IARENA_SZ (I_BSUM + 128)

__device__ __align__(256) int g_iarena[IARENA_SZ];

// ---------------- helpers -----------------------------------------------------
__device__ __forceinline__ void red4(float* a, float4 v) {
    asm volatile("red.global.add.v4.f32 [%0], {%1,%2,%3,%4};"
                 :: "l"(a), "f"(v.x), "f"(v.y), "f"(v.z), "f"(v.w) : "memory");
}
__device__ __forceinline__ float lrelu(float v) { return v > 0.f ? v : 0.2f * v; }
__device__ __forceinline__ float eluf(float v)  { return v > 0.f ? v : __expf(v) - 1.f; }

// ---------------- CSR build ---------------------------------------------------
__global__ __launch_bounds__(256) void k_hist(const int* __restrict__ dst, int* __restrict__ deg)
{
    int e = blockIdx.x * 256 + threadIdx.x;
    atomicAdd(&deg[dst[e]], 1);
}

__global__ __launch_bounds__(256) void k_blocksum(
    const int* __restrict__ deg, int* __restrict__ bsum)
{
    __shared__ int sh[256];
    int t = threadIdx.x;
    sh[t] = deg[blockIdx.x * 256 + t];
    __syncthreads();
#pragma unroll
    for (int off = 128; off; off >>= 1) {
        if (t < off) sh[t] += sh[t + off];
        __syncthreads();
    }
    if (t == 0) bsum[blockIdx.x] = sh[0];
}

__global__ __launch_bounds__(128) void k_scanbs(int* __restrict__ bsum)
{
    __shared__ int sh[128];
    int t = threadIdx.x;
    int v = bsum[t];
    sh[t] = v;
    __syncthreads();
#pragma unroll
    for (int off = 1; off < 128; off <<= 1) {
        int u = (t >= off) ? sh[t - off] : 0;
        __syncthreads();
        sh[t] += u;
        __syncthreads();
    }
    bsum[t] = sh[t] - v;
}

__global__ __launch_bounds__(256) void k_scanout(
    const int* __restrict__ deg, const int* __restrict__ bsum,
    int* __restrict__ rowptr, int* __restrict__ cur)
{
    __shared__ int sh[256];
    int t = threadIdx.x;
    int g = blockIdx.x * 256 + t;
    int v = deg[g];
    sh[t] = v;
    __syncthreads();
#pragma unroll
    for (int off = 1; off < 256; off <<= 1) {
        int u = (t >= off) ? sh[t - off] : 0;
        __syncthreads();
        sh[t] += u;
        __syncthreads();
    }
    int ex = sh[t] - v + bsum[blockIdx.x];
    rowptr[g] = ex;
    cur[g] = ex;
}

__global__ __launch_bounds__(256) void k_fillE(
    const int* __restrict__ ei, int* __restrict__ cur, int* __restrict__ csr)
{
    int e = blockIdx.x * 256 + threadIdx.x;
    int d = ei[EGZ + e];
    int p = atomicAdd(&cur[d], 1);
    csr[p] = ei[e];
}

__global__ __launch_bounds__(256) void k_fill0(
    const int* __restrict__ si, const float* __restrict__ sattr,
    int* __restrict__ cur, int* __restrict__ csr, float* __restrict__ csra)
{
    int e = blockIdx.x * 256 + threadIdx.x;
    int d = si[ESZ + e];
    int p = atomicAdd(&cur[d], 1);
    csr[p] = si[e];
    csra[p] = sattr[e];
}

// ---------------- atomic scatter (idx 1..3 raw passes) ------------------------
__global__ __launch_bounds__(256) void k_scatter(
    const int* __restrict__ src, const int* __restrict__ dst,
    const float* __restrict__ attr, const float* __restrict__ xin,
    float* __restrict__ outb)
{
    int t = blockIdx.x * 256 + threadIdx.x;
    int e = t >> 4, lane = t & 15;
    int s = src[e], d = dst[e];
    float a = attr[e];
    float4 v = ((const float4*)xin)[s * 16 + lane];
    v.x *= a; v.y *= a; v.z *= a; v.w *= a;
    red4(outb + d * 64 + lane * 4, v);
}

// CSR gather with idx0
__global__ __launch_bounds__(256) void k_gather0(
    const int* __restrict__ rowptr, const int* __restrict__ deg,
    const int* __restrict__ csr, const float* __restrict__ csra,
    const float* __restrict__ xin, float* __restrict__ outb, int doAbs)
{
    int t = blockIdx.x * 256 + threadIdx.x;
    int n = t >> 4, q = t & 15;
    int b = rowptr[n], dg = deg[n];
    float4 acc = make_float4(0.f, 0.f, 0.f, 0.f);
    for (int p = b; p < b + dg; p++) {
        int s = csr[p];
        float a = csra[p];
        float4 v = ((const float4*)xin)[s * 16 + q];
        if (doAbs) { v.x = fabsf(v.x); v.y = fabsf(v.y); v.z = fabsf(v.z); v.w = fabsf(v.w); }
        acc.x += a * v.x; acc.y += a * v.y; acc.z += a * v.z; acc.w += a * v.w;
    }
    ((float4*)outb)[n * 16 + q] = acc;
}

// ---------------- GEMM1 (64 rows/block) + fused attcoef -----------------------
// h = xin[N,64] @ W[64,256]; also as_/ad_ = sum over head slices
__global__ __launch_bounds__(256) void k_gemm_h(
    const float* __restrict__ xin, const float* __restrict__ W,
    const float* __restrict__ asrc, const float* __restrict__ adst,
    float* __restrict__ h, float* __restrict__ as_, float* __restrict__ ad_)
{
    __shared__ float xs[64 * 65];
    int t = threadIdx.x;
    int row0 = blockIdx.x * 64;
    // load 64x64 x-tile (padded stride 65)
    for (int i = t; i < 64 * 16; i += 256) {
        int r = i >> 4, c4 = i & 15;
        float4 v = ((const float4*)(xin + (size_t)(row0 + r) * 64))[c4];
        float* dp = &xs[r * 65 + c4 * 4];
        dp[0] = v.x; dp[1] = v.y; dp[2] = v.z; dp[3] = v.w;
    }
    __syncthreads();
    int tx = t & 63, ty = t >> 6;          // tx: 4 cols each; ty: 16-row group
    float4 acc[16];
#pragma unroll
    for (int r = 0; r < 16; r++) acc[r] = make_float4(0.f, 0.f, 0.f, 0.f);
    const float4* W4 = (const float4*)W;
#pragma unroll 4
    for (int k = 0; k < 64; k++) {
        float4 w = W4[k * 64 + tx];
#pragma unroll
        for (int r = 0; r < 16; r++) {
            float xv = xs[(ty * 16 + r) * 65 + k];
            acc[r].x += xv * w.x; acc[r].y += xv * w.y;
            acc[r].z += xv * w.z; acc[r].w += xv * w.w;
        }
    }
    // store h
#pragma unroll
    for (int r = 0; r < 16; r++)
        ((float4*)h)[(size_t)(row0 + ty * 16 + r) * 64 + tx] = acc[r];
    // fused attention coefficients
    float4 asv = ((const float4*)asrc)[tx];
    float4 adv = ((const float4*)adst)[tx];
    int hd = tx >> 4;
#pragma unroll
    for (int r = 0; r < 16; r++) {
        float ps = acc[r].x * asv.x + acc[r].y * asv.y + acc[r].z * asv.z + acc[r].w * asv.w;
        float pd = acc[r].x * adv.x + acc[r].y * adv.y + acc[r].z * adv.z + acc[r].w * adv.w;
#pragma unroll
        for (int o = 8; o; o >>= 1) {
            ps += __shfl_xor_sync(0xffffffffu, ps, o);
            pd += __shfl_xor_sync(0xffffffffu, pd, o);
        }
        if ((tx & 15) == 0) {
            int row = row0 + ty * 16 + r;
            as_[row * 4 + hd] = ps;
            ad_[row * 4 + hd] = pd;
        }
    }
}

// ---------------- per-node softmax over CSR (warp/node) -----------------------
// stores RAW exp per edge + self-exp + 1/denom (normalization deferred to aggr)
__global__ __launch_bounds__(256) void k_softmax(
    const int* __restrict__ rowptr, const int* __restrict__ deg, const int* __restrict__ csr,
    const float* __restrict__ as_, const float* __restrict__ ad_,
    float* __restrict__ aex, float* __restrict__ sexp, float* __restrict__ inv)
{
    int n = blockIdx.x * 8 + (threadIdx.x >> 5);
    int lane = threadIdx.x & 31;
    int b = rowptr[n], dg = deg[n];
    float4 adn = ((const float4*)ad_)[n];
    float4 asn = ((const float4*)as_)[n];
    float4 self;
    self.x = lrelu(asn.x + adn.x); self.y = lrelu(asn.y + adn.y);
    self.z = lrelu(asn.z + adn.z); self.w = lrelu(asn.w + adn.w);

    float4 mx = self;
    for (int j = lane; j < dg; j += 32) {
        float4 sv = ((const float4*)as_)[csr[b + j]];
        mx.x = fmaxf(mx.x, lrelu(sv.x + adn.x));
        mx.y = fmaxf(mx.y, lrelu(sv.y + adn.y));
        mx.z = fmaxf(mx.z, lrelu(sv.z + adn.z));
        mx.w = fmaxf(mx.w, lrelu(sv.w + adn.w));
    }
#pragma unroll
    for (int o = 16; o; o >>= 1) {
        mx.x = fmaxf(mx.x, __shfl_xor_sync(0xffffffffu, mx.x, o));
        mx.y = fmaxf(mx.y, __shfl_xor_sync(0xffffffffu, mx.y, o));
        mx.z = fmaxf(mx.z, __shfl_xor_sync(0xffffffffu, mx.z, o));
        mx.w = fmaxf(mx.w, __shfl_xor_sync(0xffffffffu, mx.w, o));
    }

    float4 sum = make_float4(0.f, 0.f, 0.f, 0.f);
    for (int j = lane; j < dg; j += 32) {
        float4 sv = ((const float4*)as_)[csr[b + j]];
        float4 ex;
        ex.x = __expf(lrelu(sv.x + adn.x) - mx.x);
        ex.y = __expf(lrelu(sv.y + adn.y) - mx.y);
        ex.z = __expf(lrelu(sv.z + adn.z) - mx.z);
        ex.w = __expf(lrelu(sv.w + adn.w) - mx.w);
        ((float4*)aex)[b + j] = ex;
        sum.x += ex.x; sum.y += ex.y; sum.z += ex.z; sum.w += ex.w;
    }
#pragma unroll
    for (int o = 16; o; o >>= 1) {
        sum.x += __shfl_xor_sync(0xffffffffu, sum.x, o);
        sum.y += __shfl_xor_sync(0xffffffffu, sum.y, o);
        sum.z += __shfl_xor_sync(0xffffffffu, sum.z, o);
        sum.w += __shfl_xor_sync(0xffffffffu, sum.w, o);
    }
    if (lane == 0) {
        float4 sex;
        sex.x = __expf(self.x - mx.x); sex.y = __expf(self.y - mx.y);
        sex.z = __expf(self.z - mx.z); sex.w = __expf(self.w - mx.w);
        float4 iv;
        iv.x = 1.f / (sum.x + sex.x); iv.y = 1.f / (sum.y + sex.y);
        iv.z = 1.f / (sum.z + sex.z); iv.w = 1.f / (sum.w + sex.w);
        ((float4*)sexp)[n] = sex;
        ((float4*)inv)[n] = iv;
    }
}

// ---------------- CSR gather aggregation: 64 threads/node ---------------------
__global__ __launch_bounds__(256) void k_aggr(
    const int* __restrict__ rowptr, const int* __restrict__ deg, const int* __restrict__ csr,
    const float* __restrict__ aex, const float* __restrict__ sexp, const float* __restrict__ inv,
    const float* __restrict__ h, float* __restrict__ att)
{
    int t = blockIdx.x * 256 + threadIdx.x;
    int n = t >> 6, gq = t & 63, hd = gq >> 4;
    int b = rowptr[n], dg = deg[n];
    float sex = sexp[n * 4 + hd];
    float iv  = inv[n * 4 + hd];
    float4 acc = ((const float4*)h)[(size_t)n * 64 + gq];
    acc.x *= sex; acc.y *= sex; acc.z *= sex; acc.w *= sex;
    for (int p = b; p < b + dg; p++) {
        int s = csr[p];
        float al = aex[p * 4 + hd];
        float4 hv = ((const float4*)h)[(size_t)s * 64 + gq];
        acc.x += al * hv.x; acc.y += al * hv.y; acc.z += al * hv.z; acc.w += al * hv.w;
    }
    acc.x *= iv; acc.y *= iv; acc.z *= iv; acc.w *= iv;
    ((float4*)att)[(size_t)n * 64 + gq] = acc;
}

// ---------------- GEMM2 + fused BN stats --------------------------------------
__global__ __launch_bounds__(256) void k_gemm_z(
    const float* __restrict__ att, const float* __restrict__ bias,
    const float* __restrict__ W, float* __restrict__ z, float* __restrict__ stats)
{
    __shared__ float As[64 * 65];
    __shared__ float red[16][64];
    int t = threadIdx.x;
    int row0 = blockIdx.x * 64;
    int tx = t & 15, ty = t >> 4;
    float4 acc[4];
    acc[0] = acc[1] = acc[2] = acc[3] = make_float4(0.f, 0.f, 0.f, 0.f);
    const float4* W4 = (const float4*)W;
    for (int kc = 0; kc < 4; kc++) {
        __syncthreads();
        for (int i = t; i < 1024; i += 256) {
            int r = i >> 4, c4 = i & 15;
            float4 v = ((const float4*)(att + (size_t)(row0 + r) * 256 + kc * 64))[c4];
            float4 b = ((const float4*)(bias + kc * 64))[c4];
            float* dp = &As[r * 65 + c4 * 4];
            dp[0] = eluf(v.x + b.x); dp[1] = eluf(v.y + b.y);
            dp[2] = eluf(v.z + b.z); dp[3] = eluf(v.w + b.w);
        }
        __syncthreads();
#pragma unroll 8
        for (int k = 0; k < 64; k++) {
            float4 w = W4[(kc * 64 + k) * 16 + tx];
#pragma unroll
            for (int ri = 0; ri < 4; ri++) {
                float av = As[(ty * 4 + ri) * 65 + k];
                acc[ri].x += av * w.x; acc[ri].y += av * w.y;
                acc[ri].z += av * w.z; acc[ri].w += av * w.w;
            }
        }
    }
#pragma unroll
    for (int ri = 0; ri < 4; ri++)
        ((float4*)z)[(size_t)(row0 + ty * 4 + ri) * 16 + tx] = acc[ri];

    float cs[4];
    cs[0] = acc[0].x + acc[1].x + acc[2].x + acc[3].x;
    cs[1] = acc[0].y + acc[1].y + acc[2].y + acc[3].y;
    cs[2] = acc[0].z + acc[1].z + acc[2].z + acc[3].z;
    cs[3] = acc[0].w + acc[1].w + acc[2].w + acc[3].w;
    __syncthreads();
#pragma unroll
    for (int c = 0; c < 4; c++) red[ty][tx * 4 + c] = cs[c];
    __syncthreads();
    if (t < 64) {
        float s = 0.f;
#pragma unroll
        for (int r = 0; r < 16; r++) s += red[r][t];
        atomicAdd(&stats[t], s);
    }
    cs[0] = acc[0].x*acc[0].x + acc[1].x*acc[1].x + acc[2].x*acc[2].x + acc[3].x*acc[3].x;
    cs[1] = acc[0].y*acc[0].y + acc[1].y*acc[1].y + acc[2].y*acc[2].y + acc[3].y*acc[3].y;
    cs[2] = acc[0].z*acc[0].z + acc[1].z*acc[1].z + acc[2].z*acc[2].z + acc[3].z*acc[3].z;
    cs[3] = acc[0].w*acc[0].w + acc[1].w*acc[1].w + acc[2].w*acc[2].w + acc[3].w*acc[3].w;
    __syncthreads();
#pragma unroll
    for (int c = 0; c < 4; c++) red[ty][tx * 4 + c] = cs[c];
    __syncthreads();
    if (t < 64) {
        float s = 0.f;
#pragma unroll
        for (int r = 0; r < 16; r++) s += red[r][t];
        atomicAdd(&stats[FF + t], s);
    }
}

// ---------------- BN apply (fused finstats; init / accumulate / pool) ---------
__global__ __launch_bounds__(256) void k_bnapply(
    const float* __restrict__ z, const float* __restrict__ stats,
    const float* __restrict__ g, const float* __restrict__ be,
    const float* __restrict__ base, const int* __restrict__ batch,
    float* __restrict__ xacc, float* __restrict__ pool, int doPool)
{
    __shared__ float sm_mu[64], sm_rs[64], sm_g[64], sm_b[64];
    int t = threadIdx.x;
    if (t < 64) {
        float mu = stats[t] * (1.f / NN);
        float var = stats[FF + t] * (1.f / NN) - mu * mu;
        sm_mu[t] = mu;
        sm_rs[t] = rsqrtf(var + BNEPS) * g[t];
        sm_g[t] = g[t];
        sm_b[t] = be[t];
    }
    __syncthreads();
    int gidx = blockIdx.x * 256 + t;          // [0, NN*16)
    int n = gidx >> 4, q = gidx & 15, f0 = q * 4;
    float4 zv = ((const float4*)z)[gidx];
    float4 v;
    v.x = (zv.x - sm_mu[f0 + 0]) * sm_rs[f0 + 0] + sm_b[f0 + 0];
    v.y = (zv.y - sm_mu[f0 + 1]) * sm_rs[f0 + 1] + sm_b[f0 + 1];
    v.z = (zv.z - sm_mu[f0 + 2]) * sm_rs[f0 + 2] + sm_b[f0 + 2];
    v.w = (zv.w - sm_mu[f0 + 3]) * sm_rs[f0 + 3] + sm_b[f0 + 3];
    float4 bv;
    if (base) bv = ((const float4*)base)[gidx];
    else      bv = ((const float4*)xacc)[gidx];
    v.x += bv.x; v.y += bv.y; v.z += bv.z; v.w += bv.w;
    ((float4*)xacc)[gidx] = v;
    if (doPool) red4(pool + batch[n] * 64 + f0, v);
}

// ---------------- fused FC head (single block, 1024 threads) ------------------
__global__ __launch_bounds__(1024) void k_head(
    const float* __restrict__ pool,
    const float* __restrict__ fc1W, const float* __restrict__ fc1b,
    const float* __restrict__ fc1g, const float* __restrict__ fc1be,
    const float* __restrict__ fc2W, const float* __restrict__ fc2b,
    const float* __restrict__ fc2g, const float* __restrict__ fc2be,
    const float* __restrict__ fc3W, const float* __restrict__ fc3b,
    const float* __restrict__ fc3g, const float* __restrict__ fc3be,
    float* __restrict__ out)
{
    extern __shared__ float sm[];
    float* sp = sm;                 // 64*65
    float* y1 = sp + 64 * 65;       // 64*257
    float* y2 = y1 + 64 * 257;      // 64*129
    int t = threadIdx.x;

    // load pooled [64,64]
    for (int i = t; i < 64 * 16; i += 1024) {
        int r = i >> 4, c4 = i & 15;
        float4 v = ((const float4*)pool)[i];
        float* dp = &sp[r * 65 + c4 * 4];
        dp[0] = v.x; dp[1] = v.y; dp[2] = v.z; dp[3] = v.w;
    }
    __syncthreads();

    // fc1: [64,64]@[64,256]
    {
        int c = t & 255, rg = t >> 8;  // 4 groups x 16 rows
        float accv[16];
        float bb = fc1b[c];
#pragma unroll
        for (int r = 0; r < 16; r++) accv[r] = bb;
        for (int k = 0; k < 64; k++) {
            float w = fc1W[k * 256 + c];
#pragma unroll
            for (int r = 0; r < 16; r++)
                accv[r] += sp[(rg * 16 + r) * 65 + k] * w;
        }
#pragma unroll
        for (int r = 0; r < 16; r++) y1[(rg * 16 + r) * 257 + c] = accv[r];
    }
    __syncthreads();
    // bn1 stats -> reuse sp[0..511]
    if (t < 256) {
        float s = 0.f, ss = 0.f;
#pragma unroll 8
        for (int r = 0; r < 64; r++) { float v = y1[r * 257 + t]; s += v; ss += v * v; }
        float mu = s * (1.f / GG);
        float var = ss * (1.f / GG) - mu * mu;
        sp[t] = mu;
        sp[256 + t] = rsqrtf(var + BNEPS) * fc1g[t];
    }
    __syncthreads();
    for (int i = t; i < 64 * 256; i += 1024) {
        int r = i >> 8, c = i & 255;
        float v = (y1[r * 257 + c] - sp[c]) * sp[256 + c] + fc1be[c];
        y1[r * 257 + c] = fmaxf(v, 0.f);
    }
    __syncthreads();

    // fc2: [64,256]@[256,128]
    {
        int c = t & 127, rg = t >> 7;  // 8 groups x 8 rows
        float accv[8];
        float bb = fc2b[c];
#pragma unroll
        for (int r = 0; r < 8; r++) accv[r] = bb;
        for (int k = 0; k < 256; k++) {
            float w = fc2W[k * 128 + c];
#pragma unroll
            for (int r = 0; r < 8; r++)
                accv[r] += y1[(rg * 8 + r) * 257 + k] * w;
        }
#pragma unroll
        for (int r = 0; r < 8; r++) y2[(rg * 8 + r) * 129 + c] = accv[r];
    }
    __syncthreads();
    if (t < 128) {
        float s = 0.f, ss = 0.f;
#pragma unroll 8
        for (int r = 0; r < 64; r++) { float v = y2[r * 129 + t]; s += v; ss += v * v; }
        float mu = s * (1.f / GG);
        float var = ss * (1.f / GG) - mu * mu;
        sp[t] = mu;
        sp[256 + t] = rsqrtf(var + BNEPS) * fc2g[t];
    }
    __syncthreads();
    for (int i = t; i < 64 * 128; i += 1024) {
        int r = i >> 7, c = i & 127;
        float v = (y2[r * 129 + c] - sp[c]) * sp[256 + c] + fc2be[c];
        y2[r * 129 + c] = fmaxf(v, 0.f);
    }
    __syncthreads();

    // fc3: [64,128]@[128,10] -> sp[640..] area reused for y3
    float* y3 = sp + 1024;
    if (t < 640) {
        int r = t / NCC, c = t % NCC;
        float acc = fc3b[c];
        for (int k = 0; k < 128; k++)
            acc += y2[r * 129 + k] * fc3W[k * NCC + c];
        y3[r * NCC + c] = acc;
    }
    __syncthreads();
    if (t < NCC) {
        float s = 0.f, ss = 0.f;
#pragma unroll 8
        for (int r = 0; r < 64; r++) { float v = y3[r * NCC + t]; s += v; ss += v * v; }
        float mu = s * (1.f / GG);
        float var = ss * (1.f / GG) - mu * mu;
        sp[t] = mu;
        sp[64 + t] = rsqrtf(var + BNEPS) * fc3g[t];
    }
    __syncthreads();
    if (t < 640) {
        int r = t / NCC, c = t % NCC;
        out[t] = (y3[r * NCC + c] - sp[c]) * sp[64 + c] + fc3be[c];
    }
}

// ---------------- host orchestration ------------------------------------------
extern "C" void kernel_launch(void* const* d_in, const int* in_sizes, int n_in,
                              void* d_out, int out_size)
{
    const float* x      = (const float*)d_in[0];
    const int*   eidx   = (const int*)d_in[1];
    const int*   batch  = (const int*)d_in[2];
    const int*   sidx   = (const int*)d_in[3];
    const float* sattr  = (const float*)d_in[4];
    const float* gatW   = (const float*)d_in[5];
    const float* gasrc  = (const float*)d_in[6];
    const float* gadst  = (const float*)d_in[7];
    const float* gatb   = (const float*)d_in[8];
    const float* mlpW   = (const float*)d_in[9];
    const float* mlpg   = (const float*)d_in[11];
    const float* mlpbe  = (const float*)d_in[12];
    const float* fc1W   = (const float*)d_in[13];
    const float* fc1b   = (const float*)d_in[14];
    const float* fc1g   = (const float*)d_in[15];
    const float* fc1be  = (const float*)d_in[16];
    const float* fc2W   = (const float*)d_in[17];
    const float* fc2b   = (const float*)d_in[18];
    const float* fc2g   = (const float*)d_in[19];
    const float* fc2be  = (const float*)d_in[20];
    const float* fc3W   = (const float*)d_in[21];
    const float* fc3b   = (const float*)d_in[22];
    const float* fc3g   = (const float*)d_in[23];
    const float* fc3be  = (const float*)d_in[24];
    float* out = (float*)d_out;

    float* A;
    cudaGetSymbolAddress((void**)&A, g_arena);
    int* IA;
    cudaGetSymbolAddress((void**)&IA, g_iarena);

    float* B0   = A + O_B0;
    float* BR   = A + O_BR;
    float* X123 = A + O_X;
    float* H    = A + O_H;
    float* ATT  = A + O_ATT;
    float* AS   = A + O_AS;
    float* AD   = A + O_AD;
    float* AEX  = A + O_AEX;
    float* SEXP = A + O_SEXP;
    float* INV  = A + O_INV;
    float* C0A  = A + O_C0A;
    float* Z    = A + O_Z;
    float* XACC = A + O_XACC;
    float* ST   = A + O_STATS;
    float* POOL = A + O_POOL;

    int* DEGE = IA + I_DEGE;
    int* CURE = IA + I_CURE;
    int* RPE  = IA + I_RPE;
    int* CSRE = IA + I_CSRE;
    int* DEG0 = IA + I_DEG0;
    int* CUR0 = IA + I_CUR0;
    int* RP0  = IA + I_RP0;
    int* CSR0 = IA + I_CSR0;
    int* BSUM = IA + I_BSUM;

    static int head_configured = 0;
    if (!head_configured) {
        cudaFuncSetAttribute(k_head, cudaFuncAttributeMaxDynamicSharedMemorySize, 120 * 1024);
        head_configured = 1;
    }

    // ---- CSR builds ----
    cudaMemsetAsync(DEGE, 0, NN * sizeof(int));
    cudaMemsetAsync(DEG0, 0, NN * sizeof(int));
    cudaMemsetAsync(ST, 0, 512 * sizeof(float));
    cudaMemsetAsync(POOL, 0, (size_t)GG * FF * sizeof(float));
    k_hist<<<EGZ / 256, 256>>>(eidx + EGZ, DEGE);
    k_hist<<<ESZ / 256, 256>>>(sidx + ESZ, DEG0);
    k_blocksum<<<NN / 256, 256>>>(DEGE, BSUM);
    k_scanbs<<<1, 128>>>(BSUM);
    k_scanout<<<NN / 256, 256>>>(DEGE, BSUM, RPE, CURE);
    k_fillE<<<EGZ / 256, 256>>>(eidx, CURE, CSRE);
    k_blocksum<<<NN / 256, 256>>>(DEG0, BSUM);
    k_scanbs<<<1, 128>>>(BSUM);
    k_scanout<<<NN / 256, 256>>>(DEG0, BSUM, RP0, CUR0);
    k_fill0<<<ESZ / 256, 256>>>(sidx, sattr, CUR0, CSR0, C0A);

    // ---- scatter stage ----
    cudaMemsetAsync(BR, 0, (size_t)3 * NN * FF * sizeof(float));
    const int SGRID = ESZ * 16 / 256;
    for (int j = 1; j <= 3; j++)
        k_scatter<<<SGRID, 256>>>(sidx + j * 2 * ESZ, sidx + j * 2 * ESZ + ESZ,
                                  sattr + j * ESZ, x, BR + (j - 1) * NN * FF);
    k_gather0<<<NN * 16 / 256, 256>>>(RP0, DEG0, CSR0, C0A, x, B0, 0);
    for (int j = 1; j <= 3; j++)
        k_gather0<<<NN * 16 / 256, 256>>>(RP0, DEG0, CSR0, C0A,
                                          BR + (j - 1) * NN * FF, X123 + (j - 1) * NN * FF, 1);

    const float* bx[4] = { B0, X123, X123 + NN * FF, X123 + 2 * NN * FF };

    // ---- 4 GAT branches ----
    for (int br = 0; br < 4; br++) {
        k_gemm_h<<<NN / 64, 256>>>(bx[br], gatW + br * FF * HFD,
                                   gasrc + br * HH * FF, gadst + br * HH * FF,
                                   H, AS, AD);
        k_softmax<<<NN / 8, 256>>>(RPE, DEGE, CSRE, AS, AD, AEX, SEXP, INV);
        k_aggr<<<NN * 64 / 256, 256>>>(RPE, DEGE, CSRE, AEX, SEXP, INV, H, ATT);
        k_gemm_z<<<NN / 64, 256>>>(ATT, gatb + br * HFD, mlpW + br * HFD * FF, Z, ST + br * 128);
        k_bnapply<<<NN * 16 / 256, 256>>>(Z, ST + br * 128, mlpg + br * FF, mlpbe + br * FF,
                                          (br == 0) ? x : nullptr, batch, XACC, POOL,
                                          (br == 3) ? 1 : 0);
    }

    // ---- fused head ----
    k_head<<<1, 1024, (64 * 65 + 64 * 257 + 64 * 129) * sizeof(float)>>>(
        POOL, fc1W, fc1b, fc1g, fc1be, fc2W, fc2b, fc2g, fc2be,
        fc3W, fc3b, fc3g, fc3be, out);
}